// round 10
// baseline (speedup 1.0000x reference)
#include <cuda_runtime.h>
#include <math_constants.h>
#include <cstdint>

#define N_TOK 4096
#define IN_DIM 256
#define HID 256
#define HEADS 8
#define HD 32
#define QBLK 128
#define KBLK 64
#define NITER (N_TOK / KBLK)
#define KSTR 36
#define VSTR 40
#define BSTR 72    // projqk/projv B-tile row stride (conflict-free: 8t+g)
#define BSTR2 73   // final B-tile row stride (breaks transposed-fill conflicts)

// Scratch (static __device__ arrays — allocation-free per harness rules)
__device__ float g_Q[HEADS * N_TOK * HD];
__device__ float g_K[HEADS * N_TOK * HD];
__device__ float g_V[HEADS * N_TOK * HD];
__device__ float g_xcat[N_TOK * HID];

// ===========================================================================
__device__ __forceinline__ uint32_t tf32r(float x) {
    uint32_t u;
    asm("cvt.rna.tf32.f32 %0, %1;" : "=r"(u) : "f"(x));
    return u;
}
__device__ __forceinline__ void split2(float v, uint32_t& hi, uint32_t& lo) {
    hi = tf32r(v);
    lo = tf32r(v - __uint_as_float(hi));
}

// D += A * B   (m16n8k8, tf32 inputs as .b32, f32 accumulate)
__device__ __forceinline__ void mma8(float* d, const uint32_t* a,
                                     uint32_t b0, uint32_t b1) {
    asm volatile(
        "mma.sync.aligned.m16n8k8.row.col.f32.tf32.tf32.f32 "
        "{%0,%1,%2,%3}, {%4,%5,%6,%7}, {%8,%9}, {%0,%1,%2,%3};"
        : "+f"(d[0]), "+f"(d[1]), "+f"(d[2]), "+f"(d[3])
        : "r"(a[0]), "r"(a[1]), "r"(a[2]), "r"(a[3]), "r"(b0), "r"(b1));
}

// ---------------------------------------------------------------------------
// Q/K projection via tf32 mma.sync (known-good from round 8)
// ---------------------------------------------------------------------------
__global__ __launch_bounds__(256) void projqk_kernel(
    const float* __restrict__ x,
    const float* __restrict__ peQ, const float* __restrict__ peK,
    const float* __restrict__ WQ, const float* __restrict__ WK,
    const float* __restrict__ Qb, const float* __restrict__ Kb,
    float* __restrict__ outQ, float* __restrict__ outK)
{
    __shared__ uint32_t As[128 * 36];
    __shared__ uint32_t Bs[32 * BSTR];

    const float* pe   = blockIdx.z ? peK : peQ;
    const float* W    = blockIdx.z ? WK  : WQ;
    const float* bias = blockIdx.z ? Kb  : Qb;
    float* out        = blockIdx.z ? outK : outQ;

    const int tid = threadIdx.x;
    const int w = tid >> 5, lane = tid & 31;
    const int g = lane >> 2, t = lane & 3;
    const int wm = w >> 1, wn = w & 1;
    const int m0 = blockIdx.x * 128;
    const int n0 = blockIdx.y * 64;

    float acc[2][4][4] = {};

    for (int k0 = 0; k0 < 1024; k0 += 32) {
        __syncthreads();
        #pragma unroll
        for (int i = 0; i < 4; i++) {
            int idx = tid + 256 * i;
            int row = idx >> 3;
            int col = (idx & 7) * 4;
            const float* src = (k0 < IN_DIM)
                ? &x[(size_t)(m0 + row) * IN_DIM + k0 + col]
                : &pe[(size_t)(m0 + row) * 768 + (k0 - IN_DIM) + col];
            float4 v = *reinterpret_cast<const float4*>(src);
            *reinterpret_cast<uint4*>(&As[row * 36 + col]) =
                make_uint4(tf32r(v.x), tf32r(v.y), tf32r(v.z), tf32r(v.w));
        }
        #pragma unroll
        for (int i = 0; i < 2; i++) {
            int idx = tid + 256 * i;
            int kk = idx >> 4;
            int c = (idx & 15) * 4;
            int col = n0 + c;
            float4 v = *reinterpret_cast<const float4*>(
                &W[((size_t)(col >> 5) * 1024 + k0 + kk) * HD + (col & 31)]);
            *reinterpret_cast<uint4*>(&Bs[kk * BSTR + c]) =
                make_uint4(tf32r(v.x), tf32r(v.y), tf32r(v.z), tf32r(v.w));
        }
        __syncthreads();

        #pragma unroll
        for (int ks = 0; ks < 4; ks++) {
            uint32_t af[2][4];
            #pragma unroll
            for (int mt = 0; mt < 2; mt++) {
                int rb = (wm * 32 + mt * 16) * 36 + ks * 8 + t;
                af[mt][0] = As[rb + g * 36];
                af[mt][1] = As[rb + (g + 8) * 36];
                af[mt][2] = As[rb + g * 36 + 4];
                af[mt][3] = As[rb + (g + 8) * 36 + 4];
            }
            #pragma unroll
            for (int nt = 0; nt < 4; nt++) {
                uint32_t b0 = Bs[(ks * 8 + t) * BSTR + wn * 32 + nt * 8 + g];
                uint32_t b1 = Bs[(ks * 8 + t + 4) * BSTR + wn * 32 + nt * 8 + g];
                mma8(acc[0][nt], af[0], b0, b1);
                mma8(acc[1][nt], af[1], b0, b1);
            }
        }
    }

    #pragma unroll
    for (int mt = 0; mt < 2; mt++) {
        int r0 = m0 + wm * 32 + mt * 16 + g;
        #pragma unroll
        for (int nt = 0; nt < 4; nt++) {
            int col = n0 + wn * 32 + nt * 8 + 2 * t;
            int hh = col >> 5, inner = col & 31;
            float bv0 = bias[col], bv1 = bias[col + 1];
            *reinterpret_cast<float2*>(
                &out[((size_t)hh * N_TOK + r0) * HD + inner]) =
                make_float2(acc[mt][nt][0] + bv0, acc[mt][nt][1] + bv1);
            *reinterpret_cast<float2*>(
                &out[((size_t)hh * N_TOK + r0 + 8) * HD + inner]) =
                make_float2(acc[mt][nt][2] + bv0, acc[mt][nt][3] + bv1);
        }
    }
}

// ---------------------------------------------------------------------------
// V projection, split-tf32 (3 MMAs: hi*hi + hi*lo + lo*hi) ~ fp32 precision.
// M=4096, N=256, K=256. CTA 64x64, K-chunk 32, 8 warps (wm 2 x wn 4),
// warp tile 32 rows x 16 cols.
// ---------------------------------------------------------------------------
__global__ __launch_bounds__(256) void projv_tc_kernel(
    const float* __restrict__ x, const float* __restrict__ W,
    const float* __restrict__ bias, float* __restrict__ out)
{
    __shared__ uint32_t Ah[64 * 36], Al[64 * 36];
    __shared__ uint32_t Bh[32 * BSTR], Bl[32 * BSTR];

    const int tid = threadIdx.x;
    const int w = tid >> 5, lane = tid & 31;
    const int g = lane >> 2, t = lane & 3;
    const int wm = w & 1, wn = w >> 1;
    const int m0 = blockIdx.x * 64;
    const int n0 = blockIdx.y * 64;

    float acc[2][2][4] = {};

    for (int k0 = 0; k0 < 256; k0 += 32) {
        __syncthreads();
        #pragma unroll
        for (int i = 0; i < 2; i++) {
            int idx = tid + 256 * i;
            int row = idx >> 3;
            int col = (idx & 7) * 4;
            float4 v = *reinterpret_cast<const float4*>(
                &x[(size_t)(m0 + row) * IN_DIM + k0 + col]);
            uint4 h, l;
            split2(v.x, h.x, l.x); split2(v.y, h.y, l.y);
            split2(v.z, h.z, l.z); split2(v.w, h.w, l.w);
            *reinterpret_cast<uint4*>(&Ah[row * 36 + col]) = h;
            *reinterpret_cast<uint4*>(&Al[row * 36 + col]) = l;
        }
        #pragma unroll
        for (int i = 0; i < 2; i++) {
            int idx = tid + 256 * i;
            int kk = idx >> 4;
            int c = (idx & 15) * 4;
            int col = n0 + c;
            float4 v = *reinterpret_cast<const float4*>(
                &W[((size_t)(col >> 5) * 256 + k0 + kk) * HD + (col & 31)]);
            uint4 h, l;
            split2(v.x, h.x, l.x); split2(v.y, h.y, l.y);
            split2(v.z, h.z, l.z); split2(v.w, h.w, l.w);
            *reinterpret_cast<uint4*>(&Bh[kk * BSTR + c]) = h;
            *reinterpret_cast<uint4*>(&Bl[kk * BSTR + c]) = l;
        }
        __syncthreads();

        #pragma unroll
        for (int ks = 0; ks < 4; ks++) {
            uint32_t afh[2][4], afl[2][4];
            #pragma unroll
            for (int mt = 0; mt < 2; mt++) {
                int rb = (wm * 32 + mt * 16) * 36 + ks * 8 + t;
                afh[mt][0] = Ah[rb + g * 36];
                afh[mt][1] = Ah[rb + (g + 8) * 36];
                afh[mt][2] = Ah[rb + g * 36 + 4];
                afh[mt][3] = Ah[rb + (g + 8) * 36 + 4];
                afl[mt][0] = Al[rb + g * 36];
                afl[mt][1] = Al[rb + (g + 8) * 36];
                afl[mt][2] = Al[rb + g * 36 + 4];
                afl[mt][3] = Al[rb + (g + 8) * 36 + 4];
            }
            #pragma unroll
            for (int nt = 0; nt < 2; nt++) {
                int cb = wn * 16 + nt * 8 + g;
                uint32_t b0h = Bh[(ks * 8 + t) * BSTR + cb];
                uint32_t b1h = Bh[(ks * 8 + t + 4) * BSTR + cb];
                uint32_t b0l = Bl[(ks * 8 + t) * BSTR + cb];
                uint32_t b1l = Bl[(ks * 8 + t + 4) * BSTR + cb];
                #pragma unroll
                for (int mt = 0; mt < 2; mt++) {
                    mma8(acc[mt][nt], afh[mt], b0h, b1h);
                    mma8(acc[mt][nt], afh[mt], b0l, b1l);
                    mma8(acc[mt][nt], afl[mt], b0h, b1h);
                }
            }
        }
    }

    #pragma unroll
    for (int mt = 0; mt < 2; mt++) {
        int r0 = m0 + wm * 32 + mt * 16 + g;
        #pragma unroll
        for (int nt = 0; nt < 2; nt++) {
            int col = n0 + wn * 16 + nt * 8 + 2 * t;
            int hh = col >> 5, inner = col & 31;
            float bv0 = bias[col], bv1 = bias[col + 1];
            *reinterpret_cast<float2*>(
                &out[((size_t)hh * N_TOK + r0) * HD + inner]) =
                make_float2(acc[mt][nt][0] + bv0, acc[mt][nt][1] + bv1);
            *reinterpret_cast<float2*>(
                &out[((size_t)hh * N_TOK + r0 + 8) * HD + inner]) =
                make_float2(acc[mt][nt][2] + bv0, acc[mt][nt][3] + bv1);
        }
    }
}

// ---------------------------------------------------------------------------
// Final linear, split-tf32: out = xcat @ lw^T + lb.  Same tiling as projv_tc.
// B fill transposes lw rows (contiguous along k) into [kk][col] tiles.
// ---------------------------------------------------------------------------
__global__ __launch_bounds__(256) void final_tc_kernel(
    const float* __restrict__ xcat, const float* __restrict__ lw,
    const float* __restrict__ lb, float* __restrict__ out)
{
    __shared__ uint32_t Ah[64 * 36], Al[64 * 36];
    __shared__ uint32_t Bh[32 * BSTR2], Bl[32 * BSTR2];

    const int tid = threadIdx.x;
    const int w = tid >> 5, lane = tid & 31;
    const int g = lane >> 2, t = lane & 3;
    const int wm = w & 1, wn = w >> 1;
    const int m0 = blockIdx.x * 64;
    const int n0 = blockIdx.y * 64;

    float acc[2][2][4] = {};

    for (int k0 = 0; k0 < 256; k0 += 32) {
        __syncthreads();
        #pragma unroll
        for (int i = 0; i < 2; i++) {
            int idx = tid + 256 * i;
            int row = idx >> 3;
            int col = (idx & 7) * 4;
            float4 v = *reinterpret_cast<const float4*>(
                &xcat[(size_t)(m0 + row) * HID + k0 + col]);
            uint4 h, l;
            split2(v.x, h.x, l.x); split2(v.y, h.y, l.y);
            split2(v.z, h.z, l.z); split2(v.w, h.w, l.w);
            *reinterpret_cast<uint4*>(&Ah[row * 36 + col]) = h;
            *reinterpret_cast<uint4*>(&Al[row * 36 + col]) = l;
        }
        #pragma unroll
        for (int i = 0; i < 2; i++) {
            int idx = tid + 256 * i;
            int c = idx >> 3;                 // 0..63 (output col within tile)
            int kq = (idx & 7) * 4;           // k base
            float4 v = *reinterpret_cast<const float4*>(
                &lw[(size_t)(n0 + c) * HID + k0 + kq]);
            uint32_t h0, l0v, h1, l1v, h2, l2v, h3, l3v;
            split2(v.x, h0, l0v); split2(v.y, h1, l1v);
            split2(v.z, h2, l2v); split2(v.w, h3, l3v);
            Bh[(kq + 0) * BSTR2 + c] = h0;  Bl[(kq + 0) * BSTR2 + c] = l0v;
            Bh[(kq + 1) * BSTR2 + c] = h1;  Bl[(kq + 1) * BSTR2 + c] = l1v;
            Bh[(kq + 2) * BSTR2 + c] = h2;  Bl[(kq + 2) * BSTR2 + c] = l2v;
            Bh[(kq + 3) * BSTR2 + c] = h3;  Bl[(kq + 3) * BSTR2 + c] = l3v;
        }
        __syncthreads();

        #pragma unroll
        for (int ks = 0; ks < 4; ks++) {
            uint32_t afh[2][4], afl[2][4];
            #pragma unroll
            for (int mt = 0; mt < 2; mt++) {
                int rb = (wm * 32 + mt * 16) * 36 + ks * 8 + t;
                afh[mt][0] = Ah[rb + g * 36];
                afh[mt][1] = Ah[rb + (g + 8) * 36];
                afh[mt][2] = Ah[rb + g * 36 + 4];
                afh[mt][3] = Ah[rb + (g + 8) * 36 + 4];
                afl[mt][0] = Al[rb + g * 36];
                afl[mt][1] = Al[rb + (g + 8) * 36];
                afl[mt][2] = Al[rb + g * 36 + 4];
                afl[mt][3] = Al[rb + (g + 8) * 36 + 4];
            }
            #pragma unroll
            for (int nt = 0; nt < 2; nt++) {
                int cb = wn * 16 + nt * 8 + g;
                uint32_t b0h = Bh[(ks * 8 + t) * BSTR2 + cb];
                uint32_t b1h = Bh[(ks * 8 + t + 4) * BSTR2 + cb];
                uint32_t b0l = Bl[(ks * 8 + t) * BSTR2 + cb];
                uint32_t b1l = Bl[(ks * 8 + t + 4) * BSTR2 + cb];
                #pragma unroll
                for (int mt = 0; mt < 2; mt++) {
                    mma8(acc[mt][nt], afh[mt], b0h, b1h);
                    mma8(acc[mt][nt], afh[mt], b0l, b1l);
                    mma8(acc[mt][nt], afl[mt], b0h, b1h);
                }
            }
        }
    }

    #pragma unroll
    for (int mt = 0; mt < 2; mt++) {
        int r0 = m0 + wm * 32 + mt * 16 + g;
        #pragma unroll
        for (int nt = 0; nt < 2; nt++) {
            int col = n0 + wn * 16 + nt * 8 + 2 * t;
            float bv0 = lb[col], bv1 = lb[col + 1];
            *reinterpret_cast<float2*>(&out[(size_t)r0 * HID + col]) =
                make_float2(acc[mt][nt][0] + bv0, acc[mt][nt][1] + bv1);
            *reinterpret_cast<float2*>(&out[(size_t)(r0 + 8) * HID + col]) =
                make_float2(acc[mt][nt][2] + bv0, acc[mt][nt][3] + bv1);
        }
    }
}

// ---------------------------------------------------------------------------
// Flash attention, tf32 mma.sync, m-doubled + register-pipelined KV loads.
// Grid (N/128, HEADS); block 256 (8 warps).
// ---------------------------------------------------------------------------
__global__ __launch_bounds__(256) void attn_mma_kernel(
    const float* __restrict__ Qg, const float* __restrict__ Kg,
    const float* __restrict__ Vg, float* __restrict__ xcat)
{
    __shared__ uint32_t Ks[KBLK * KSTR];
    __shared__ uint32_t Vs[KBLK * VSTR];
    __shared__ float sO[QBLK * 34];
    __shared__ float sL[QBLK];

    const int tid = threadIdx.x;
    const int w = tid >> 5;
    const int lane = tid & 31;
    const int g = lane >> 2;
    const int t = lane & 3;
    const int h = blockIdx.y;
    const int q0 = blockIdx.x * QBLK;
    const int wm = w >> 1;
    const int m0 = wm * 32;
    const int c0 = (w & 1) * 32;

    const float* Qh = Qg + (size_t)h * N_TOK * HD;
    const float* Kh = Kg + (size_t)h * N_TOK * HD;
    const float* Vh = Vg + (size_t)h * N_TOK * HD;

    // 1/sqrt(256) * log2(e): exp(x*0.0625) == exp2(x*SC2)
    const float SC2 = 0.0625f * 1.4426950408889634f;

    // ---- Q fragments: 2 m-tiles (persistent, scaled, tf32-rounded) ----
    uint32_t qf[2][4][4];
    #pragma unroll
    for (int mt = 0; mt < 2; mt++) {
        const float* qr0 = Qh + (size_t)(q0 + m0 + mt * 16 + g) * HD;
        const float* qr1 = qr0 + 8 * HD;
        #pragma unroll
        for (int s = 0; s < 4; s++) {
            qf[mt][s][0] = tf32r(qr0[8 * s + t] * SC2);
            qf[mt][s][1] = tf32r(qr1[8 * s + t] * SC2);
            qf[mt][s][2] = tf32r(qr0[8 * s + t + 4] * SC2);
            qf[mt][s][3] = tf32r(qr1[8 * s + t + 4] * SC2);
        }
    }

    float of[2][4][4] = {};
    float l[2][2] = {};

    const unsigned srcLo = (unsigned)((lane & ~3) | (t >> 1));
    const unsigned srcHi = srcLo | 2u;
    const bool odd = t & 1;

    // ---- register-pipelined KV tile loads ----
    const int frow = tid >> 3;            // 0..31
    const int fcol = (tid & 7) * 4;       // 0,4,...,28
    float4 kr0, kr1, vr0, vr1;
    {
        const float* kp = Kh + (size_t)frow * HD + fcol;
        const float* vp = Vh + (size_t)frow * HD + fcol;
        kr0 = *reinterpret_cast<const float4*>(kp);
        kr1 = *reinterpret_cast<const float4*>(kp + 32 * HD);
        vr0 = *reinterpret_cast<const float4*>(vp);
        vr1 = *reinterpret_cast<const float4*>(vp + 32 * HD);
    }

    for (int kb = 0; kb < NITER; kb++) {
        __syncthreads();   // previous compute done reading tiles
        *reinterpret_cast<uint4*>(&Ks[frow * KSTR + fcol]) =
            make_uint4(tf32r(kr0.x), tf32r(kr0.y), tf32r(kr0.z), tf32r(kr0.w));
        *reinterpret_cast<uint4*>(&Ks[(frow + 32) * KSTR + fcol]) =
            make_uint4(tf32r(kr1.x), tf32r(kr1.y), tf32r(kr1.z), tf32r(kr1.w));
        *reinterpret_cast<uint4*>(&Vs[frow * VSTR + fcol]) =
            make_uint4(tf32r(vr0.x), tf32r(vr0.y), tf32r(vr0.z), tf32r(vr0.w));
        *reinterpret_cast<uint4*>(&Vs[(frow + 32) * VSTR + fcol]) =
            make_uint4(tf32r(vr1.x), tf32r(vr1.y), tf32r(vr1.z), tf32r(vr1.w));
        __syncthreads();

        if (kb + 1 < NITER) {   // prefetch next tile during compute
            const float* kp = Kh + (size_t)((kb + 1) * KBLK + frow) * HD + fcol;
            const float* vp = Vh + (size_t)((kb + 1) * KBLK + frow) * HD + fcol;
            kr0 = *reinterpret_cast<const float4*>(kp);
            kr1 = *reinterpret_cast<const float4*>(kp + 32 * HD);
            vr0 = *reinterpret_cast<const float4*>(vp);
            vr1 = *reinterpret_cast<const float4*>(vp + 32 * HD);
        }

        #pragma unroll
        for (int j = 0; j < 4; j++) {
            const uint32_t* kbp = &Ks[(c0 + 8 * j + g) * KSTR + t];
            uint32_t kw[8];
            #pragma unroll
            for (int s = 0; s < 4; s++) {
                kw[2 * s]     = kbp[8 * s];
                kw[2 * s + 1] = kbp[8 * s + 4];
            }
            float sf[2][4] = {};
            #pragma unroll
            for (int mt = 0; mt < 2; mt++)
                #pragma unroll
                for (int s = 0; s < 4; s++)
                    mma8(sf[mt], qf[mt][s], kw[2 * s], kw[2 * s + 1]);

            const uint32_t* vb0 = &Vs[(c0 + 8 * j + t) * VSTR + g];
            const uint32_t* vb1 = vb0 + 4 * VSTR;
            uint32_t vw0[4], vw1[4];
            #pragma unroll
            for (int nn = 0; nn < 4; nn++) { vw0[nn] = vb0[8 * nn]; vw1[nn] = vb1[8 * nn]; }

            #pragma unroll
            for (int mt = 0; mt < 2; mt++) {
                float e0 = exp2f(sf[mt][0]);
                float e1 = exp2f(sf[mt][1]);
                float e2 = exp2f(sf[mt][2]);
                float e3 = exp2f(sf[mt][3]);
                l[mt][0] += e0 + e1;
                l[mt][1] += e2 + e3;

                float u0 = __shfl_sync(0xffffffffu, e0, srcLo);
                float u1 = __shfl_sync(0xffffffffu, e1, srcLo);
                float w0 = __shfl_sync(0xffffffffu, e0, srcHi);
                float w1 = __shfl_sync(0xffffffffu, e1, srcHi);
                float x0 = __shfl_sync(0xffffffffu, e2, srcLo);
                float x1 = __shfl_sync(0xffffffffu, e3, srcLo);
                float y0 = __shfl_sync(0xffffffffu, e2, srcHi);
                float y1 = __shfl_sync(0xffffffffu, e3, srcHi);
                uint32_t pa[4];
                pa[0] = tf32r(odd ? u1 : u0);
                pa[1] = tf32r(odd ? x1 : x0);
                pa[2] = tf32r(odd ? w1 : w0);
                pa[3] = tf32r(odd ? y1 : y0);

                #pragma unroll
                for (int nn = 0; nn < 4; nn++)
                    mma8(of[mt][nn], pa, vw0[nn], vw1[nn]);
            }
        }
    }

    // ---- epilogue ----
    __syncwarp();
    #pragma unroll
    for (int mt = 0; mt < 2; mt++) {
        l[mt][0] += __shfl_xor_sync(0xffffffffu, l[mt][0], 1);
        l[mt][0] += __shfl_xor_sync(0xffffffffu, l[mt][0], 2);
        l[mt][1] += __shfl_xor_sync(0xffffffffu, l[mt][1], 1);
        l[mt][1] += __shfl_xor_sync(0xffffffffu, l[mt][1], 2);
    }

    if (w & 1) {
        #pragma unroll
        for (int mt = 0; mt < 2; mt++) {
            int r = m0 + mt * 16 + g;
            if (t == 0) { sL[r] = l[mt][0]; sL[r + 8] = l[mt][1]; }
            #pragma unroll
            for (int nn = 0; nn < 4; nn++) {
                *reinterpret_cast<float2*>(&sO[r * 34 + 8 * nn + 2 * t]) =
                    make_float2(of[mt][nn][0], of[mt][nn][1]);
                *reinterpret_cast<float2*>(&sO[(r + 8) * 34 + 8 * nn + 2 * t]) =
                    make_float2(of[mt][nn][2], of[mt][nn][3]);
            }
        }
    }
    __syncthreads();
    if (!(w & 1)) {
        #pragma unroll
        for (int mt = 0; mt < 2; mt++) {
            int r = m0 + mt * 16 + g;
            float L0 = l[mt][0] + sL[r];
            float L1 = l[mt][1] + sL[r + 8];
            float i0 = 1.0f / L0, i1 = 1.0f / L1;
            #pragma unroll
            for (int nn = 0; nn < 4; nn++) {
                float2 a = *reinterpret_cast<const float2*>(&sO[r * 34 + 8 * nn + 2 * t]);
                float2 b = *reinterpret_cast<const float2*>(&sO[(r + 8) * 34 + 8 * nn + 2 * t]);
                *reinterpret_cast<float2*>(
                    &xcat[(size_t)(q0 + r) * HID + h * HD + 8 * nn + 2 * t]) =
                    make_float2((of[mt][nn][0] + a.x) * i0, (of[mt][nn][1] + a.y) * i0);
                *reinterpret_cast<float2*>(
                    &xcat[(size_t)(q0 + r + 8) * HID + h * HD + 8 * nn + 2 * t]) =
                    make_float2((of[mt][nn][2] + b.x) * i1, (of[mt][nn][3] + b.y) * i1);
            }
        }
    }
}

// ---------------------------------------------------------------------------
extern "C" void kernel_launch(void* const* d_in, const int* in_sizes, int n_in,
                              void* d_out, int out_size)
{
    const float* x   = (const float*)d_in[0];
    const float* peQ = (const float*)d_in[1];
    const float* peK = (const float*)d_in[2];
    const float* WQ  = (const float*)d_in[4];
    const float* WK  = (const float*)d_in[5];
    const float* WV  = (const float*)d_in[6];
    const float* Qb  = (const float*)d_in[7];
    const float* Kb  = (const float*)d_in[8];
    const float* Vb  = (const float*)d_in[9];
    const float* lw  = (const float*)d_in[10];
    const float* lb  = (const float*)d_in[11];
    float* out = (float*)d_out;

    float *qp, *kp, *vp, *xc;
    cudaGetSymbolAddress((void**)&qp, g_Q);
    cudaGetSymbolAddress((void**)&kp, g_K);
    cudaGetSymbolAddress((void**)&vp, g_V);
    cudaGetSymbolAddress((void**)&xc, g_xcat);

    projqk_kernel<<<dim3(N_TOK / 128, HID / 64, 2), 256>>>(
        x, peQ, peK, WQ, WK, Qb, Kb, qp, kp);
    projv_tc_kernel<<<dim3(N_TOK / 64, HID / 64), 256>>>(x, WV, Vb, vp);
    attn_mma_kernel<<<dim3(N_TOK / QBLK, HEADS), 256>>>(qp, kp, vp, xc);
    final_tc_kernel<<<dim3(N_TOK / 64, HID / 64), 256>>>(xc, lw, lb, out);
}

// round 11
// speedup vs baseline: 1.1729x; 1.1729x over previous
#include <cuda_runtime.h>
#include <math_constants.h>
#include <cstdint>

#define N_TOK 4096
#define IN_DIM 256
#define HID 256
#define HEADS 8
#define HD 32
#define QBLK 128
#define KBLK 64
#define NITER (N_TOK / KBLK)
#define KSTR 36
#define VSTR 40
#define BSTR 72    // projqk/projv B-tile row stride (conflict-free: 8t+g)
#define BSTR2 73   // final B-tile row stride (breaks transposed-fill conflicts)

// Scratch (static __device__ arrays — allocation-free per harness rules)
__device__ float g_Q[HEADS * N_TOK * HD];
__device__ float g_K[HEADS * N_TOK * HD];
__device__ float g_V[HEADS * N_TOK * HD];
__device__ float g_xcat[N_TOK * HID];

// ===========================================================================
__device__ __forceinline__ uint32_t tf32r(float x) {
    uint32_t u;
    asm("cvt.rna.tf32.f32 %0, %1;" : "=r"(u) : "f"(x));
    return u;
}
__device__ __forceinline__ void split2(float v, uint32_t& hi, uint32_t& lo) {
    hi = tf32r(v);
    lo = tf32r(v - __uint_as_float(hi));
}

// D += A * B   (m16n8k8, tf32 inputs as .b32, f32 accumulate)
__device__ __forceinline__ void mma8(float* d, const uint32_t* a,
                                     uint32_t b0, uint32_t b1) {
    asm volatile(
        "mma.sync.aligned.m16n8k8.row.col.f32.tf32.tf32.f32 "
        "{%0,%1,%2,%3}, {%4,%5,%6,%7}, {%8,%9}, {%0,%1,%2,%3};"
        : "+f"(d[0]), "+f"(d[1]), "+f"(d[2]), "+f"(d[3])
        : "r"(a[0]), "r"(a[1]), "r"(a[2]), "r"(a[3]), "r"(b0), "r"(b1));
}

// ---------------------------------------------------------------------------
// Q/K projection via tf32 mma.sync (known-good from round 8)
// ---------------------------------------------------------------------------
__global__ __launch_bounds__(256) void projqk_kernel(
    const float* __restrict__ x,
    const float* __restrict__ peQ, const float* __restrict__ peK,
    const float* __restrict__ WQ, const float* __restrict__ WK,
    const float* __restrict__ Qb, const float* __restrict__ Kb,
    float* __restrict__ outQ, float* __restrict__ outK)
{
    __shared__ uint32_t As[128 * 36];
    __shared__ uint32_t Bs[32 * BSTR];

    const float* pe   = blockIdx.z ? peK : peQ;
    const float* W    = blockIdx.z ? WK  : WQ;
    const float* bias = blockIdx.z ? Kb  : Qb;
    float* out        = blockIdx.z ? outK : outQ;

    const int tid = threadIdx.x;
    const int w = tid >> 5, lane = tid & 31;
    const int g = lane >> 2, t = lane & 3;
    const int wm = w >> 1, wn = w & 1;
    const int m0 = blockIdx.x * 128;
    const int n0 = blockIdx.y * 64;

    float acc[2][4][4] = {};

    for (int k0 = 0; k0 < 1024; k0 += 32) {
        __syncthreads();
        #pragma unroll
        for (int i = 0; i < 4; i++) {
            int idx = tid + 256 * i;
            int row = idx >> 3;
            int col = (idx & 7) * 4;
            const float* src = (k0 < IN_DIM)
                ? &x[(size_t)(m0 + row) * IN_DIM + k0 + col]
                : &pe[(size_t)(m0 + row) * 768 + (k0 - IN_DIM) + col];
            float4 v = *reinterpret_cast<const float4*>(src);
            *reinterpret_cast<uint4*>(&As[row * 36 + col]) =
                make_uint4(tf32r(v.x), tf32r(v.y), tf32r(v.z), tf32r(v.w));
        }
        #pragma unroll
        for (int i = 0; i < 2; i++) {
            int idx = tid + 256 * i;
            int kk = idx >> 4;
            int c = (idx & 15) * 4;
            int col = n0 + c;
            float4 v = *reinterpret_cast<const float4*>(
                &W[((size_t)(col >> 5) * 1024 + k0 + kk) * HD + (col & 31)]);
            *reinterpret_cast<uint4*>(&Bs[kk * BSTR + c]) =
                make_uint4(tf32r(v.x), tf32r(v.y), tf32r(v.z), tf32r(v.w));
        }
        __syncthreads();

        #pragma unroll
        for (int ks = 0; ks < 4; ks++) {
            uint32_t af[2][4];
            #pragma unroll
            for (int mt = 0; mt < 2; mt++) {
                int rb = (wm * 32 + mt * 16) * 36 + ks * 8 + t;
                af[mt][0] = As[rb + g * 36];
                af[mt][1] = As[rb + (g + 8) * 36];
                af[mt][2] = As[rb + g * 36 + 4];
                af[mt][3] = As[rb + (g + 8) * 36 + 4];
            }
            #pragma unroll
            for (int nt = 0; nt < 4; nt++) {
                uint32_t b0 = Bs[(ks * 8 + t) * BSTR + wn * 32 + nt * 8 + g];
                uint32_t b1 = Bs[(ks * 8 + t + 4) * BSTR + wn * 32 + nt * 8 + g];
                mma8(acc[0][nt], af[0], b0, b1);
                mma8(acc[1][nt], af[1], b0, b1);
            }
        }
    }

    #pragma unroll
    for (int mt = 0; mt < 2; mt++) {
        int r0 = m0 + wm * 32 + mt * 16 + g;
        #pragma unroll
        for (int nt = 0; nt < 4; nt++) {
            int col = n0 + wn * 32 + nt * 8 + 2 * t;
            int hh = col >> 5, inner = col & 31;
            float bv0 = bias[col], bv1 = bias[col + 1];
            *reinterpret_cast<float2*>(
                &out[((size_t)hh * N_TOK + r0) * HD + inner]) =
                make_float2(acc[mt][nt][0] + bv0, acc[mt][nt][1] + bv1);
            *reinterpret_cast<float2*>(
                &out[((size_t)hh * N_TOK + r0 + 8) * HD + inner]) =
                make_float2(acc[mt][nt][2] + bv0, acc[mt][nt][3] + bv1);
        }
    }
}

// ---------------------------------------------------------------------------
// V projection, split-tf32 (3 MMAs: hi*hi + hi*lo + lo*hi) ~ fp32 precision.
// (known-good from round 10: ~14us)
// ---------------------------------------------------------------------------
__global__ __launch_bounds__(256) void projv_tc_kernel(
    const float* __restrict__ x, const float* __restrict__ W,
    const float* __restrict__ bias, float* __restrict__ out)
{
    __shared__ uint32_t Ah[64 * 36], Al[64 * 36];
    __shared__ uint32_t Bh[32 * BSTR], Bl[32 * BSTR];

    const int tid = threadIdx.x;
    const int w = tid >> 5, lane = tid & 31;
    const int g = lane >> 2, t = lane & 3;
    const int wm = w & 1, wn = w >> 1;
    const int m0 = blockIdx.x * 64;
    const int n0 = blockIdx.y * 64;

    float acc[2][2][4] = {};

    for (int k0 = 0; k0 < 256; k0 += 32) {
        __syncthreads();
        #pragma unroll
        for (int i = 0; i < 2; i++) {
            int idx = tid + 256 * i;
            int row = idx >> 3;
            int col = (idx & 7) * 4;
            float4 v = *reinterpret_cast<const float4*>(
                &x[(size_t)(m0 + row) * IN_DIM + k0 + col]);
            uint4 h, l;
            split2(v.x, h.x, l.x); split2(v.y, h.y, l.y);
            split2(v.z, h.z, l.z); split2(v.w, h.w, l.w);
            *reinterpret_cast<uint4*>(&Ah[row * 36 + col]) = h;
            *reinterpret_cast<uint4*>(&Al[row * 36 + col]) = l;
        }
        #pragma unroll
        for (int i = 0; i < 2; i++) {
            int idx = tid + 256 * i;
            int kk = idx >> 4;
            int c = (idx & 15) * 4;
            int col = n0 + c;
            float4 v = *reinterpret_cast<const float4*>(
                &W[((size_t)(col >> 5) * 256 + k0 + kk) * HD + (col & 31)]);
            uint4 h, l;
            split2(v.x, h.x, l.x); split2(v.y, h.y, l.y);
            split2(v.z, h.z, l.z); split2(v.w, h.w, l.w);
            *reinterpret_cast<uint4*>(&Bh[kk * BSTR + c]) = h;
            *reinterpret_cast<uint4*>(&Bl[kk * BSTR + c]) = l;
        }
        __syncthreads();

        #pragma unroll
        for (int ks = 0; ks < 4; ks++) {
            uint32_t afh[2][4], afl[2][4];
            #pragma unroll
            for (int mt = 0; mt < 2; mt++) {
                int rb = (wm * 32 + mt * 16) * 36 + ks * 8 + t;
                afh[mt][0] = Ah[rb + g * 36];
                afh[mt][1] = Ah[rb + (g + 8) * 36];
                afh[mt][2] = Ah[rb + g * 36 + 4];
                afh[mt][3] = Ah[rb + (g + 8) * 36 + 4];
                afl[mt][0] = Al[rb + g * 36];
                afl[mt][1] = Al[rb + (g + 8) * 36];
                afl[mt][2] = Al[rb + g * 36 + 4];
                afl[mt][3] = Al[rb + (g + 8) * 36 + 4];
            }
            #pragma unroll
            for (int nt = 0; nt < 2; nt++) {
                int cb = wn * 16 + nt * 8 + g;
                uint32_t b0h = Bh[(ks * 8 + t) * BSTR + cb];
                uint32_t b1h = Bh[(ks * 8 + t + 4) * BSTR + cb];
                uint32_t b0l = Bl[(ks * 8 + t) * BSTR + cb];
                uint32_t b1l = Bl[(ks * 8 + t + 4) * BSTR + cb];
                #pragma unroll
                for (int mt = 0; mt < 2; mt++) {
                    mma8(acc[mt][nt], afh[mt], b0h, b1h);
                    mma8(acc[mt][nt], afh[mt], b0l, b1l);
                    mma8(acc[mt][nt], afl[mt], b0h, b1h);
                }
            }
        }
    }

    #pragma unroll
    for (int mt = 0; mt < 2; mt++) {
        int r0 = m0 + wm * 32 + mt * 16 + g;
        #pragma unroll
        for (int nt = 0; nt < 2; nt++) {
            int col = n0 + wn * 16 + nt * 8 + 2 * t;
            int hh = col >> 5, inner = col & 31;
            float bv0 = bias[col], bv1 = bias[col + 1];
            *reinterpret_cast<float2*>(
                &out[((size_t)hh * N_TOK + r0) * HD + inner]) =
                make_float2(acc[mt][nt][0] + bv0, acc[mt][nt][1] + bv1);
            *reinterpret_cast<float2*>(
                &out[((size_t)hh * N_TOK + r0 + 8) * HD + inner]) =
                make_float2(acc[mt][nt][2] + bv0, acc[mt][nt][3] + bv1);
        }
    }
}

// ---------------------------------------------------------------------------
// Final linear, split-tf32: out = xcat @ lw^T + lb (known-good, 19.2us)
// ---------------------------------------------------------------------------
__global__ __launch_bounds__(256) void final_tc_kernel(
    const float* __restrict__ xcat, const float* __restrict__ lw,
    const float* __restrict__ lb, float* __restrict__ out)
{
    __shared__ uint32_t Ah[64 * 36], Al[64 * 36];
    __shared__ uint32_t Bh[32 * BSTR2], Bl[32 * BSTR2];

    const int tid = threadIdx.x;
    const int w = tid >> 5, lane = tid & 31;
    const int g = lane >> 2, t = lane & 3;
    const int wm = w & 1, wn = w >> 1;
    const int m0 = blockIdx.x * 64;
    const int n0 = blockIdx.y * 64;

    float acc[2][2][4] = {};

    for (int k0 = 0; k0 < 256; k0 += 32) {
        __syncthreads();
        #pragma unroll
        for (int i = 0; i < 2; i++) {
            int idx = tid + 256 * i;
            int row = idx >> 3;
            int col = (idx & 7) * 4;
            float4 v = *reinterpret_cast<const float4*>(
                &xcat[(size_t)(m0 + row) * HID + k0 + col]);
            uint4 h, l;
            split2(v.x, h.x, l.x); split2(v.y, h.y, l.y);
            split2(v.z, h.z, l.z); split2(v.w, h.w, l.w);
            *reinterpret_cast<uint4*>(&Ah[row * 36 + col]) = h;
            *reinterpret_cast<uint4*>(&Al[row * 36 + col]) = l;
        }
        #pragma unroll
        for (int i = 0; i < 2; i++) {
            int idx = tid + 256 * i;
            int c = idx >> 3;
            int kq = (idx & 7) * 4;
            float4 v = *reinterpret_cast<const float4*>(
                &lw[(size_t)(n0 + c) * HID + k0 + kq]);
            uint32_t h0, l0v, h1, l1v, h2, l2v, h3, l3v;
            split2(v.x, h0, l0v); split2(v.y, h1, l1v);
            split2(v.z, h2, l2v); split2(v.w, h3, l3v);
            Bh[(kq + 0) * BSTR2 + c] = h0;  Bl[(kq + 0) * BSTR2 + c] = l0v;
            Bh[(kq + 1) * BSTR2 + c] = h1;  Bl[(kq + 1) * BSTR2 + c] = l1v;
            Bh[(kq + 2) * BSTR2 + c] = h2;  Bl[(kq + 2) * BSTR2 + c] = l2v;
            Bh[(kq + 3) * BSTR2 + c] = h3;  Bl[(kq + 3) * BSTR2 + c] = l3v;
        }
        __syncthreads();

        #pragma unroll
        for (int ks = 0; ks < 4; ks++) {
            uint32_t afh[2][4], afl[2][4];
            #pragma unroll
            for (int mt = 0; mt < 2; mt++) {
                int rb = (wm * 32 + mt * 16) * 36 + ks * 8 + t;
                afh[mt][0] = Ah[rb + g * 36];
                afh[mt][1] = Ah[rb + (g + 8) * 36];
                afh[mt][2] = Ah[rb + g * 36 + 4];
                afh[mt][3] = Ah[rb + (g + 8) * 36 + 4];
                afl[mt][0] = Al[rb + g * 36];
                afl[mt][1] = Al[rb + (g + 8) * 36];
                afl[mt][2] = Al[rb + g * 36 + 4];
                afl[mt][3] = Al[rb + (g + 8) * 36 + 4];
            }
            #pragma unroll
            for (int nt = 0; nt < 2; nt++) {
                int cb = wn * 16 + nt * 8 + g;
                uint32_t b0h = Bh[(ks * 8 + t) * BSTR2 + cb];
                uint32_t b1h = Bh[(ks * 8 + t + 4) * BSTR2 + cb];
                uint32_t b0l = Bl[(ks * 8 + t) * BSTR2 + cb];
                uint32_t b1l = Bl[(ks * 8 + t + 4) * BSTR2 + cb];
                #pragma unroll
                for (int mt = 0; mt < 2; mt++) {
                    mma8(acc[mt][nt], afh[mt], b0h, b1h);
                    mma8(acc[mt][nt], afh[mt], b0l, b1l);
                    mma8(acc[mt][nt], afl[mt], b0h, b1h);
                }
            }
        }
    }

    #pragma unroll
    for (int mt = 0; mt < 2; mt++) {
        int r0 = m0 + wm * 32 + mt * 16 + g;
        #pragma unroll
        for (int nt = 0; nt < 2; nt++) {
            int col = n0 + wn * 16 + nt * 8 + 2 * t;
            float bv0 = lb[col], bv1 = lb[col + 1];
            *reinterpret_cast<float2*>(&out[(size_t)r0 * HID + col]) =
                make_float2(acc[mt][nt][0] + bv0, acc[mt][nt][1] + bv1);
            *reinterpret_cast<float2*>(&out[(size_t)(r0 + 8) * HID + col]) =
                make_float2(acc[mt][nt][2] + bv0, acc[mt][nt][3] + bv1);
        }
    }
}

// ---------------------------------------------------------------------------
// Flash attention, tf32 mma.sync, m-doubled (round-9 structure: NO register
// prefetch — it cost occupancy). exp2f with log2(e) folded into Q scale.
// Grid (N/128, HEADS); block 256 (8 warps).
// ---------------------------------------------------------------------------
__global__ __launch_bounds__(256) void attn_mma_kernel(
    const float* __restrict__ Qg, const float* __restrict__ Kg,
    const float* __restrict__ Vg, float* __restrict__ xcat)
{
    __shared__ uint32_t Ks[KBLK * KSTR];
    __shared__ uint32_t Vs[KBLK * VSTR];
    __shared__ float sO[QBLK * 34];
    __shared__ float sL[QBLK];

    const int tid = threadIdx.x;
    const int w = tid >> 5;
    const int lane = tid & 31;
    const int g = lane >> 2;
    const int t = lane & 3;
    const int h = blockIdx.y;
    const int q0 = blockIdx.x * QBLK;
    const int wm = w >> 1;
    const int m0 = wm * 32;
    const int c0 = (w & 1) * 32;

    const float* Qh = Qg + (size_t)h * N_TOK * HD;
    const float* Kh = Kg + (size_t)h * N_TOK * HD;
    const float* Vh = Vg + (size_t)h * N_TOK * HD;

    // 1/sqrt(256) * log2(e): exp(x*0.0625) == exp2(x*SC2)
    const float SC2 = 0.0625f * 1.4426950408889634f;

    uint32_t qf[2][4][4];
    #pragma unroll
    for (int mt = 0; mt < 2; mt++) {
        const float* qr0 = Qh + (size_t)(q0 + m0 + mt * 16 + g) * HD;
        const float* qr1 = qr0 + 8 * HD;
        #pragma unroll
        for (int s = 0; s < 4; s++) {
            qf[mt][s][0] = tf32r(qr0[8 * s + t] * SC2);
            qf[mt][s][1] = tf32r(qr1[8 * s + t] * SC2);
            qf[mt][s][2] = tf32r(qr0[8 * s + t + 4] * SC2);
            qf[mt][s][3] = tf32r(qr1[8 * s + t + 4] * SC2);
        }
    }

    float of[2][4][4] = {};
    float l[2][2] = {};

    const unsigned srcLo = (unsigned)((lane & ~3) | (t >> 1));
    const unsigned srcHi = srcLo | 2u;
    const bool odd = t & 1;

    for (int kb = 0; kb < NITER; kb++) {
        __syncthreads();
        #pragma unroll
        for (int i = 0; i < 2; i++) {
            int idx = tid + 256 * i;
            int row = idx >> 3, cc = (idx & 7) << 2;
            const float4 kv = *reinterpret_cast<const float4*>(
                Kh + (size_t)(kb * KBLK + row) * HD + cc);
            *reinterpret_cast<uint4*>(&Ks[row * KSTR + cc]) =
                make_uint4(tf32r(kv.x), tf32r(kv.y), tf32r(kv.z), tf32r(kv.w));
            const float4 vv = *reinterpret_cast<const float4*>(
                Vh + (size_t)(kb * KBLK + row) * HD + cc);
            *reinterpret_cast<uint4*>(&Vs[row * VSTR + cc]) =
                make_uint4(tf32r(vv.x), tf32r(vv.y), tf32r(vv.z), tf32r(vv.w));
        }
        __syncthreads();

        #pragma unroll
        for (int j = 0; j < 4; j++) {
            const uint32_t* kbp = &Ks[(c0 + 8 * j + g) * KSTR + t];
            uint32_t kw[8];
            #pragma unroll
            for (int s = 0; s < 4; s++) {
                kw[2 * s]     = kbp[8 * s];
                kw[2 * s + 1] = kbp[8 * s + 4];
            }
            float sf[2][4] = {};
            #pragma unroll
            for (int mt = 0; mt < 2; mt++)
                #pragma unroll
                for (int s = 0; s < 4; s++)
                    mma8(sf[mt], qf[mt][s], kw[2 * s], kw[2 * s + 1]);

            const uint32_t* vb0 = &Vs[(c0 + 8 * j + t) * VSTR + g];
            const uint32_t* vb1 = vb0 + 4 * VSTR;
            uint32_t vw0[4], vw1[4];
            #pragma unroll
            for (int nn = 0; nn < 4; nn++) { vw0[nn] = vb0[8 * nn]; vw1[nn] = vb1[8 * nn]; }

            #pragma unroll
            for (int mt = 0; mt < 2; mt++) {
                float e0 = exp2f(sf[mt][0]);
                float e1 = exp2f(sf[mt][1]);
                float e2 = exp2f(sf[mt][2]);
                float e3 = exp2f(sf[mt][3]);
                l[mt][0] += e0 + e1;
                l[mt][1] += e2 + e3;

                float u0 = __shfl_sync(0xffffffffu, e0, srcLo);
                float u1 = __shfl_sync(0xffffffffu, e1, srcLo);
                float w0 = __shfl_sync(0xffffffffu, e0, srcHi);
                float w1 = __shfl_sync(0xffffffffu, e1, srcHi);
                float x0 = __shfl_sync(0xffffffffu, e2, srcLo);
                float x1 = __shfl_sync(0xffffffffu, e3, srcLo);
                float y0 = __shfl_sync(0xffffffffu, e2, srcHi);
                float y1 = __shfl_sync(0xffffffffu, e3, srcHi);
                uint32_t pa[4];
                pa[0] = tf32r(odd ? u1 : u0);
                pa[1] = tf32r(odd ? x1 : x0);
                pa[2] = tf32r(odd ? w1 : w0);
                pa[3] = tf32r(odd ? y1 : y0);

                #pragma unroll
                for (int nn = 0; nn < 4; nn++)
                    mma8(of[mt][nn], pa, vw0[nn], vw1[nn]);
            }
        }
    }

    // ---- epilogue ----
    __syncwarp();
    #pragma unroll
    for (int mt = 0; mt < 2; mt++) {
        l[mt][0] += __shfl_xor_sync(0xffffffffu, l[mt][0], 1);
        l[mt][0] += __shfl_xor_sync(0xffffffffu, l[mt][0], 2);
        l[mt][1] += __shfl_xor_sync(0xffffffffu, l[mt][1], 1);
        l[mt][1] += __shfl_xor_sync(0xffffffffu, l[mt][1], 2);
    }

    if (w & 1) {
        #pragma unroll
        for (int mt = 0; mt < 2; mt++) {
            int r = m0 + mt * 16 + g;
            if (t == 0) { sL[r] = l[mt][0]; sL[r + 8] = l[mt][1]; }
            #pragma unroll
            for (int nn = 0; nn < 4; nn++) {
                *reinterpret_cast<float2*>(&sO[r * 34 + 8 * nn + 2 * t]) =
                    make_float2(of[mt][nn][0], of[mt][nn][1]);
                *reinterpret_cast<float2*>(&sO[(r + 8) * 34 + 8 * nn + 2 * t]) =
                    make_float2(of[mt][nn][2], of[mt][nn][3]);
            }
        }
    }
    __syncthreads();
    if (!(w & 1)) {
        #pragma unroll
        for (int mt = 0; mt < 2; mt++) {
            int r = m0 + mt * 16 + g;
            float L0 = l[mt][0] + sL[r];
            float L1 = l[mt][1] + sL[r + 8];
            float i0 = 1.0f / L0, i1 = 1.0f / L1;
            #pragma unroll
            for (int nn = 0; nn < 4; nn++) {
                float2 a = *reinterpret_cast<const float2*>(&sO[r * 34 + 8 * nn + 2 * t]);
                float2 b = *reinterpret_cast<const float2*>(&sO[(r + 8) * 34 + 8 * nn + 2 * t]);
                *reinterpret_cast<float2*>(
                    &xcat[(size_t)(q0 + r) * HID + h * HD + 8 * nn + 2 * t]) =
                    make_float2((of[mt][nn][0] + a.x) * i0, (of[mt][nn][1] + a.y) * i0);
                *reinterpret_cast<float2*>(
                    &xcat[(size_t)(q0 + r + 8) * HID + h * HD + 8 * nn + 2 * t]) =
                    make_float2((of[mt][nn][2] + b.x) * i1, (of[mt][nn][3] + b.y) * i1);
            }
        }
    }
}

// ---------------------------------------------------------------------------
extern "C" void kernel_launch(void* const* d_in, const int* in_sizes, int n_in,
                              void* d_out, int out_size)
{
    const float* x   = (const float*)d_in[0];
    const float* peQ = (const float*)d_in[1];
    const float* peK = (const float*)d_in[2];
    const float* WQ  = (const float*)d_in[4];
    const float* WK  = (const float*)d_in[5];
    const float* WV  = (const float*)d_in[6];
    const float* Qb  = (const float*)d_in[7];
    const float* Kb  = (const float*)d_in[8];
    const float* Vb  = (const float*)d_in[9];
    const float* lw  = (const float*)d_in[10];
    const float* lb  = (const float*)d_in[11];
    float* out = (float*)d_out;

    float *qp, *kp, *vp, *xc;
    cudaGetSymbolAddress((void**)&qp, g_Q);
    cudaGetSymbolAddress((void**)&kp, g_K);
    cudaGetSymbolAddress((void**)&vp, g_V);
    cudaGetSymbolAddress((void**)&xc, g_xcat);

    projqk_kernel<<<dim3(N_TOK / 128, HID / 64, 2), 256>>>(
        x, peQ, peK, WQ, WK, Qb, Kb, qp, kp);
    projv_tc_kernel<<<dim3(N_TOK / 64, HID / 64), 256>>>(x, WV, Vb, vp);
    attn_mma_kernel<<<dim3(N_TOK / QBLK, HEADS), 256>>>(qp, kp, vp, xc);
    final_tc_kernel<<<dim3(N_TOK / 64, HID / 64), 256>>>(xc, lw, lb, out);
}

// round 12
// speedup vs baseline: 1.2492x; 1.0651x over previous
#include <cuda_runtime.h>
#include <math_constants.h>
#include <cstdint>

#define N_TOK 4096
#define IN_DIM 256
#define HID 256
#define HEADS 8
#define HD 32
#define QBLK 128
#define KBLK 64
#define NITER (N_TOK / KBLK)
#define KSTR 36
#define VSTR 40
#define BSTR 72    // projqk/projv B-tile row stride (conflict-free: 8t+g)
#define BSTR2 73   // final B-tile row stride (breaks transposed-fill conflicts)

// attn SMEM layout (bytes): double-buffered [Ks | Vs] stages; epilogue aliases
#define KBYTES (KBLK * KSTR * 4)          // 9216
#define VBYTES (KBLK * VSTR * 4)          // 10240
#define STAGE_BYTES (KBYTES + VBYTES)     // 19456
#define SBUF_BYTES (2 * STAGE_BYTES)      // 38912

// 1/sqrt(256) * log2(e): exp(x*0.0625) == exp2(x*SC2Q)
#define SC2Q (0.0625f * 1.4426950408889634f)

// Scratch (static __device__ arrays — allocation-free per harness rules)
// g_Q holds tf32-rounded, SC2Q-pre-scaled Q bits; g_K/g_V hold tf32-rounded bits.
__device__ float g_Q[HEADS * N_TOK * HD];
__device__ float g_K[HEADS * N_TOK * HD];
__device__ float g_V[HEADS * N_TOK * HD];
__device__ float g_xcat[N_TOK * HID];

// ===========================================================================
__device__ __forceinline__ uint32_t tf32r(float x) {
    uint32_t u;
    asm("cvt.rna.tf32.f32 %0, %1;" : "=r"(u) : "f"(x));
    return u;
}
__device__ __forceinline__ void split2(float v, uint32_t& hi, uint32_t& lo) {
    hi = tf32r(v);
    lo = tf32r(v - __uint_as_float(hi));
}
__device__ __forceinline__ uint32_t smem_u32(const void* p) {
    uint32_t a;
    asm("{ .reg .u64 t; cvta.to.shared.u64 t, %1; cvt.u32.u64 %0, t; }" : "=r"(a) : "l"(p));
    return a;
}
__device__ __forceinline__ void cp16(uint32_t saddr, const void* gaddr) {
    asm volatile("cp.async.cg.shared.global [%0], [%1], 16;"
                 :: "r"(saddr), "l"(gaddr) : "memory");
}
#define CP_COMMIT() asm volatile("cp.async.commit_group;" ::: "memory")
#define CP_WAIT0()  asm volatile("cp.async.wait_group 0;" ::: "memory")

// D += A * B   (m16n8k8, tf32 inputs as .b32, f32 accumulate)
__device__ __forceinline__ void mma8(float* d, const uint32_t* a,
                                     uint32_t b0, uint32_t b1) {
    asm volatile(
        "mma.sync.aligned.m16n8k8.row.col.f32.tf32.tf32.f32 "
        "{%0,%1,%2,%3}, {%4,%5,%6,%7}, {%8,%9}, {%0,%1,%2,%3};"
        : "+f"(d[0]), "+f"(d[1]), "+f"(d[2]), "+f"(d[3])
        : "r"(a[0]), "r"(a[1]), "r"(a[2]), "r"(a[3]), "r"(b0), "r"(b1));
}

// ---------------------------------------------------------------------------
// Q/K projection via tf32 mma.sync. Epilogue writes tf32-rounded bits
// (Q pre-scaled by SC2Q) — bit-identical to rounding in the attn kernel,
// and enables raw cp.async KV fills there.
// ---------------------------------------------------------------------------
__global__ __launch_bounds__(256) void projqk_kernel(
    const float* __restrict__ x,
    const float* __restrict__ peQ, const float* __restrict__ peK,
    const float* __restrict__ WQ, const float* __restrict__ WK,
    const float* __restrict__ Qb, const float* __restrict__ Kb,
    float* __restrict__ outQ, float* __restrict__ outK)
{
    __shared__ uint32_t As[128 * 36];
    __shared__ uint32_t Bs[32 * BSTR];

    const float* pe   = blockIdx.z ? peK : peQ;
    const float* W    = blockIdx.z ? WK  : WQ;
    const float* bias = blockIdx.z ? Kb  : Qb;
    float* out        = blockIdx.z ? outK : outQ;
    const float osc   = blockIdx.z ? 1.0f : SC2Q;

    const int tid = threadIdx.x;
    const int w = tid >> 5, lane = tid & 31;
    const int g = lane >> 2, t = lane & 3;
    const int wm = w >> 1, wn = w & 1;
    const int m0 = blockIdx.x * 128;
    const int n0 = blockIdx.y * 64;

    float acc[2][4][4] = {};

    for (int k0 = 0; k0 < 1024; k0 += 32) {
        __syncthreads();
        #pragma unroll
        for (int i = 0; i < 4; i++) {
            int idx = tid + 256 * i;
            int row = idx >> 3;
            int col = (idx & 7) * 4;
            const float* src = (k0 < IN_DIM)
                ? &x[(size_t)(m0 + row) * IN_DIM + k0 + col]
                : &pe[(size_t)(m0 + row) * 768 + (k0 - IN_DIM) + col];
            float4 v = *reinterpret_cast<const float4*>(src);
            *reinterpret_cast<uint4*>(&As[row * 36 + col]) =
                make_uint4(tf32r(v.x), tf32r(v.y), tf32r(v.z), tf32r(v.w));
        }
        #pragma unroll
        for (int i = 0; i < 2; i++) {
            int idx = tid + 256 * i;
            int kk = idx >> 4;
            int c = (idx & 15) * 4;
            int col = n0 + c;
            float4 v = *reinterpret_cast<const float4*>(
                &W[((size_t)(col >> 5) * 1024 + k0 + kk) * HD + (col & 31)]);
            *reinterpret_cast<uint4*>(&Bs[kk * BSTR + c]) =
                make_uint4(tf32r(v.x), tf32r(v.y), tf32r(v.z), tf32r(v.w));
        }
        __syncthreads();

        #pragma unroll
        for (int ks = 0; ks < 4; ks++) {
            uint32_t af[2][4];
            #pragma unroll
            for (int mt = 0; mt < 2; mt++) {
                int rb = (wm * 32 + mt * 16) * 36 + ks * 8 + t;
                af[mt][0] = As[rb + g * 36];
                af[mt][1] = As[rb + (g + 8) * 36];
                af[mt][2] = As[rb + g * 36 + 4];
                af[mt][3] = As[rb + (g + 8) * 36 + 4];
            }
            #pragma unroll
            for (int nt = 0; nt < 4; nt++) {
                uint32_t b0 = Bs[(ks * 8 + t) * BSTR + wn * 32 + nt * 8 + g];
                uint32_t b1 = Bs[(ks * 8 + t + 4) * BSTR + wn * 32 + nt * 8 + g];
                mma8(acc[0][nt], af[0], b0, b1);
                mma8(acc[1][nt], af[1], b0, b1);
            }
        }
    }

    #pragma unroll
    for (int mt = 0; mt < 2; mt++) {
        int r0 = m0 + wm * 32 + mt * 16 + g;
        #pragma unroll
        for (int nt = 0; nt < 4; nt++) {
            int col = n0 + wn * 32 + nt * 8 + 2 * t;
            int hh = col >> 5, inner = col & 31;
            float bv0 = bias[col], bv1 = bias[col + 1];
            *reinterpret_cast<float2*>(
                &out[((size_t)hh * N_TOK + r0) * HD + inner]) =
                make_float2(__uint_as_float(tf32r((acc[mt][nt][0] + bv0) * osc)),
                            __uint_as_float(tf32r((acc[mt][nt][1] + bv1) * osc)));
            *reinterpret_cast<float2*>(
                &out[((size_t)hh * N_TOK + r0 + 8) * HD + inner]) =
                make_float2(__uint_as_float(tf32r((acc[mt][nt][2] + bv0) * osc)),
                            __uint_as_float(tf32r((acc[mt][nt][3] + bv1) * osc)));
        }
    }
}

// ---------------------------------------------------------------------------
// V projection, split-tf32. Epilogue writes tf32-rounded bits (bit-identical
// to the rounding attn previously applied on V).
// ---------------------------------------------------------------------------
__global__ __launch_bounds__(256) void projv_tc_kernel(
    const float* __restrict__ x, const float* __restrict__ W,
    const float* __restrict__ bias, float* __restrict__ out)
{
    __shared__ uint32_t Ah[64 * 36], Al[64 * 36];
    __shared__ uint32_t Bh[32 * BSTR], Bl[32 * BSTR];

    const int tid = threadIdx.x;
    const int w = tid >> 5, lane = tid & 31;
    const int g = lane >> 2, t = lane & 3;
    const int wm = w & 1, wn = w >> 1;
    const int m0 = blockIdx.x * 64;
    const int n0 = blockIdx.y * 64;

    float acc[2][2][4] = {};

    for (int k0 = 0; k0 < 256; k0 += 32) {
        __syncthreads();
        #pragma unroll
        for (int i = 0; i < 2; i++) {
            int idx = tid + 256 * i;
            int row = idx >> 3;
            int col = (idx & 7) * 4;
            float4 v = *reinterpret_cast<const float4*>(
                &x[(size_t)(m0 + row) * IN_DIM + k0 + col]);
            uint4 h, l;
            split2(v.x, h.x, l.x); split2(v.y, h.y, l.y);
            split2(v.z, h.z, l.z); split2(v.w, h.w, l.w);
            *reinterpret_cast<uint4*>(&Ah[row * 36 + col]) = h;
            *reinterpret_cast<uint4*>(&Al[row * 36 + col]) = l;
        }
        #pragma unroll
        for (int i = 0; i < 2; i++) {
            int idx = tid + 256 * i;
            int kk = idx >> 4;
            int c = (idx & 15) * 4;
            int col = n0 + c;
            float4 v = *reinterpret_cast<const float4*>(
                &W[((size_t)(col >> 5) * 256 + k0 + kk) * HD + (col & 31)]);
            uint4 h, l;
            split2(v.x, h.x, l.x); split2(v.y, h.y, l.y);
            split2(v.z, h.z, l.z); split2(v.w, h.w, l.w);
            *reinterpret_cast<uint4*>(&Bh[kk * BSTR + c]) = h;
            *reinterpret_cast<uint4*>(&Bl[kk * BSTR + c]) = l;
        }
        __syncthreads();

        #pragma unroll
        for (int ks = 0; ks < 4; ks++) {
            uint32_t afh[2][4], afl[2][4];
            #pragma unroll
            for (int mt = 0; mt < 2; mt++) {
                int rb = (wm * 32 + mt * 16) * 36 + ks * 8 + t;
                afh[mt][0] = Ah[rb + g * 36];
                afh[mt][1] = Ah[rb + (g + 8) * 36];
                afh[mt][2] = Ah[rb + g * 36 + 4];
                afh[mt][3] = Ah[rb + (g + 8) * 36 + 4];
                afl[mt][0] = Al[rb + g * 36];
                afl[mt][1] = Al[rb + (g + 8) * 36];
                afl[mt][2] = Al[rb + g * 36 + 4];
                afl[mt][3] = Al[rb + (g + 8) * 36 + 4];
            }
            #pragma unroll
            for (int nt = 0; nt < 2; nt++) {
                int cb = wn * 16 + nt * 8 + g;
                uint32_t b0h = Bh[(ks * 8 + t) * BSTR + cb];
                uint32_t b1h = Bh[(ks * 8 + t + 4) * BSTR + cb];
                uint32_t b0l = Bl[(ks * 8 + t) * BSTR + cb];
                uint32_t b1l = Bl[(ks * 8 + t + 4) * BSTR + cb];
                #pragma unroll
                for (int mt = 0; mt < 2; mt++) {
                    mma8(acc[mt][nt], afh[mt], b0h, b1h);
                    mma8(acc[mt][nt], afh[mt], b0l, b1l);
                    mma8(acc[mt][nt], afl[mt], b0h, b1h);
                }
            }
        }
    }

    #pragma unroll
    for (int mt = 0; mt < 2; mt++) {
        int r0 = m0 + wm * 32 + mt * 16 + g;
        #pragma unroll
        for (int nt = 0; nt < 2; nt++) {
            int col = n0 + wn * 16 + nt * 8 + 2 * t;
            int hh = col >> 5, inner = col & 31;
            float bv0 = bias[col], bv1 = bias[col + 1];
            *reinterpret_cast<float2*>(
                &out[((size_t)hh * N_TOK + r0) * HD + inner]) =
                make_float2(__uint_as_float(tf32r(acc[mt][nt][0] + bv0)),
                            __uint_as_float(tf32r(acc[mt][nt][1] + bv1)));
            *reinterpret_cast<float2*>(
                &out[((size_t)hh * N_TOK + r0 + 8) * HD + inner]) =
                make_float2(__uint_as_float(tf32r(acc[mt][nt][2] + bv0)),
                            __uint_as_float(tf32r(acc[mt][nt][3] + bv1)));
        }
    }
}

// ---------------------------------------------------------------------------
// Final linear, split-tf32: out = xcat @ lw^T + lb (known-good, 19us)
// ---------------------------------------------------------------------------
__global__ __launch_bounds__(256) void final_tc_kernel(
    const float* __restrict__ xcat, const float* __restrict__ lw,
    const float* __restrict__ lb, float* __restrict__ out)
{
    __shared__ uint32_t Ah[64 * 36], Al[64 * 36];
    __shared__ uint32_t Bh[32 * BSTR2], Bl[32 * BSTR2];

    const int tid = threadIdx.x;
    const int w = tid >> 5, lane = tid & 31;
    const int g = lane >> 2, t = lane & 3;
    const int wm = w & 1, wn = w >> 1;
    const int m0 = blockIdx.x * 64;
    const int n0 = blockIdx.y * 64;

    float acc[2][2][4] = {};

    for (int k0 = 0; k0 < 256; k0 += 32) {
        __syncthreads();
        #pragma unroll
        for (int i = 0; i < 2; i++) {
            int idx = tid + 256 * i;
            int row = idx >> 3;
            int col = (idx & 7) * 4;
            float4 v = *reinterpret_cast<const float4*>(
                &xcat[(size_t)(m0 + row) * HID + k0 + col]);
            uint4 h, l;
            split2(v.x, h.x, l.x); split2(v.y, h.y, l.y);
            split2(v.z, h.z, l.z); split2(v.w, h.w, l.w);
            *reinterpret_cast<uint4*>(&Ah[row * 36 + col]) = h;
            *reinterpret_cast<uint4*>(&Al[row * 36 + col]) = l;
        }
        #pragma unroll
        for (int i = 0; i < 2; i++) {
            int idx = tid + 256 * i;
            int c = idx >> 3;
            int kq = (idx & 7) * 4;
            float4 v = *reinterpret_cast<const float4*>(
                &lw[(size_t)(n0 + c) * HID + k0 + kq]);
            uint32_t h0, l0v, h1, l1v, h2, l2v, h3, l3v;
            split2(v.x, h0, l0v); split2(v.y, h1, l1v);
            split2(v.z, h2, l2v); split2(v.w, h3, l3v);
            Bh[(kq + 0) * BSTR2 + c] = h0;  Bl[(kq + 0) * BSTR2 + c] = l0v;
            Bh[(kq + 1) * BSTR2 + c] = h1;  Bl[(kq + 1) * BSTR2 + c] = l1v;
            Bh[(kq + 2) * BSTR2 + c] = h2;  Bl[(kq + 2) * BSTR2 + c] = l2v;
            Bh[(kq + 3) * BSTR2 + c] = h3;  Bl[(kq + 3) * BSTR2 + c] = l3v;
        }
        __syncthreads();

        #pragma unroll
        for (int ks = 0; ks < 4; ks++) {
            uint32_t afh[2][4], afl[2][4];
            #pragma unroll
            for (int mt = 0; mt < 2; mt++) {
                int rb = (wm * 32 + mt * 16) * 36 + ks * 8 + t;
                afh[mt][0] = Ah[rb + g * 36];
                afh[mt][1] = Ah[rb + (g + 8) * 36];
                afh[mt][2] = Ah[rb + g * 36 + 4];
                afh[mt][3] = Ah[rb + (g + 8) * 36 + 4];
                afl[mt][0] = Al[rb + g * 36];
                afl[mt][1] = Al[rb + (g + 8) * 36];
                afl[mt][2] = Al[rb + g * 36 + 4];
                afl[mt][3] = Al[rb + (g + 8) * 36 + 4];
            }
            #pragma unroll
            for (int nt = 0; nt < 2; nt++) {
                int cb = wn * 16 + nt * 8 + g;
                uint32_t b0h = Bh[(ks * 8 + t) * BSTR2 + cb];
                uint32_t b1h = Bh[(ks * 8 + t + 4) * BSTR2 + cb];
                uint32_t b0l = Bl[(ks * 8 + t) * BSTR2 + cb];
                uint32_t b1l = Bl[(ks * 8 + t + 4) * BSTR2 + cb];
                #pragma unroll
                for (int mt = 0; mt < 2; mt++) {
                    mma8(acc[mt][nt], afh[mt], b0h, b1h);
                    mma8(acc[mt][nt], afh[mt], b0l, b1l);
                    mma8(acc[mt][nt], afl[mt], b0h, b1h);
                }
            }
        }
    }

    #pragma unroll
    for (int mt = 0; mt < 2; mt++) {
        int r0 = m0 + wm * 32 + mt * 16 + g;
        #pragma unroll
        for (int nt = 0; nt < 2; nt++) {
            int col = n0 + wn * 16 + nt * 8 + 2 * t;
            float bv0 = lb[col], bv1 = lb[col + 1];
            *reinterpret_cast<float2*>(&out[(size_t)r0 * HID + col]) =
                make_float2(acc[mt][nt][0] + bv0, acc[mt][nt][1] + bv1);
            *reinterpret_cast<float2*>(&out[(size_t)(r0 + 8) * HID + col]) =
                make_float2(acc[mt][nt][2] + bv0, acc[mt][nt][3] + bv1);
        }
    }
}

// ---------------------------------------------------------------------------
// Flash attention, tf32 mma.sync, m-doubled + cp.async double-buffered KV
// (no register staging -> occupancy preserved). Inputs are pre-rounded tf32
// bits (Q pre-scaled by SC2Q), so fills are raw 16B copies.
// Epilogue scratch aliases the KV buffers (used only after the loop).
// Grid (N/128, HEADS); block 256 (8 warps).
// ---------------------------------------------------------------------------
__global__ __launch_bounds__(256) void attn_mma_kernel(
    const float* __restrict__ Qg, const float* __restrict__ Kg,
    const float* __restrict__ Vg, float* __restrict__ xcat)
{
    __shared__ __align__(16) char sbuf[SBUF_BYTES];
    const uint32_t sb = smem_u32(sbuf);

    const int tid = threadIdx.x;
    const int w = tid >> 5;
    const int lane = tid & 31;
    const int g = lane >> 2;
    const int t = lane & 3;
    const int h = blockIdx.y;
    const int q0 = blockIdx.x * QBLK;
    const int wm = w >> 1;
    const int m0 = wm * 32;
    const int c0 = (w & 1) * 32;

    const float* Qh = Qg + (size_t)h * N_TOK * HD;
    const float* Kh = Kg + (size_t)h * N_TOK * HD;
    const float* Vh = Vg + (size_t)h * N_TOK * HD;

    // ---- Q fragments: pre-scaled + pre-rounded bits, direct load ----
    uint32_t qf[2][4][4];
    #pragma unroll
    for (int mt = 0; mt < 2; mt++) {
        const float* qr0 = Qh + (size_t)(q0 + m0 + mt * 16 + g) * HD;
        const float* qr1 = qr0 + 8 * HD;
        #pragma unroll
        for (int s = 0; s < 4; s++) {
            qf[mt][s][0] = __float_as_uint(qr0[8 * s + t]);
            qf[mt][s][1] = __float_as_uint(qr1[8 * s + t]);
            qf[mt][s][2] = __float_as_uint(qr0[8 * s + t + 4]);
            qf[mt][s][3] = __float_as_uint(qr1[8 * s + t + 4]);
        }
    }

    float of[2][4][4] = {};
    float l[2][2] = {};

    const unsigned srcLo = (unsigned)((lane & ~3) | (t >> 1));
    const unsigned srcHi = srcLo | 2u;
    const bool odd = t & 1;

    // ---- cp.async fill geometry: each thread copies 4x16B per tile ----
    const int frow = tid >> 3;            // 0..31
    const int fb = (tid & 7) * 16;        // byte offset within 128B row

    // preload tile 0 into stage 0
    {
        const char* kg = (const char*)(Kh + (size_t)frow * HD) + fb;
        const char* vg = (const char*)(Vh + (size_t)frow * HD) + fb;
        cp16(sb + frow * (KSTR * 4) + fb, kg);
        cp16(sb + (frow + 32) * (KSTR * 4) + fb, kg + 32 * HD * 4);
        cp16(sb + KBYTES + frow * (VSTR * 4) + fb, vg);
        cp16(sb + KBYTES + (frow + 32) * (VSTR * 4) + fb, vg + 32 * HD * 4);
        CP_COMMIT();
    }

    for (int kb = 0; kb < NITER; kb++) {
        CP_WAIT0();
        __syncthreads();   // tile kb visible to all; all warps done with kb-1

        const int stage = kb & 1;
        if (kb + 1 < NITER) {
            const uint32_t nb = sb + (stage ^ 1) * STAGE_BYTES;
            const char* kg = (const char*)(Kh + (size_t)((kb + 1) * KBLK + frow) * HD) + fb;
            const char* vg = (const char*)(Vh + (size_t)((kb + 1) * KBLK + frow) * HD) + fb;
            cp16(nb + frow * (KSTR * 4) + fb, kg);
            cp16(nb + (frow + 32) * (KSTR * 4) + fb, kg + 32 * HD * 4);
            cp16(nb + KBYTES + frow * (VSTR * 4) + fb, vg);
            cp16(nb + KBYTES + (frow + 32) * (VSTR * 4) + fb, vg + 32 * HD * 4);
            CP_COMMIT();
        }

        const uint32_t* Ksp = reinterpret_cast<const uint32_t*>(sbuf + stage * STAGE_BYTES);
        const uint32_t* Vsp = reinterpret_cast<const uint32_t*>(sbuf + stage * STAGE_BYTES + KBYTES);

        #pragma unroll
        for (int j = 0; j < 4; j++) {
            const uint32_t* kbp = &Ksp[(c0 + 8 * j + g) * KSTR + t];
            uint32_t kw[8];
            #pragma unroll
            for (int s = 0; s < 4; s++) {
                kw[2 * s]     = kbp[8 * s];
                kw[2 * s + 1] = kbp[8 * s + 4];
            }
            float sf[2][4] = {};
            #pragma unroll
            for (int mt = 0; mt < 2; mt++)
                #pragma unroll
                for (int s = 0; s < 4; s++)
                    mma8(sf[mt], qf[mt][s], kw[2 * s], kw[2 * s + 1]);

            const uint32_t* vb0 = &Vsp[(c0 + 8 * j + t) * VSTR + g];
            const uint32_t* vb1 = vb0 + 4 * VSTR;
            uint32_t vw0[4], vw1[4];
            #pragma unroll
            for (int nn = 0; nn < 4; nn++) { vw0[nn] = vb0[8 * nn]; vw1[nn] = vb1[8 * nn]; }

            #pragma unroll
            for (int mt = 0; mt < 2; mt++) {
                float e0 = exp2f(sf[mt][0]);
                float e1 = exp2f(sf[mt][1]);
                float e2 = exp2f(sf[mt][2]);
                float e3 = exp2f(sf[mt][3]);
                l[mt][0] += e0 + e1;
                l[mt][1] += e2 + e3;

                float u0 = __shfl_sync(0xffffffffu, e0, srcLo);
                float u1 = __shfl_sync(0xffffffffu, e1, srcLo);
                float w0 = __shfl_sync(0xffffffffu, e0, srcHi);
                float w1 = __shfl_sync(0xffffffffu, e1, srcHi);
                float x0 = __shfl_sync(0xffffffffu, e2, srcLo);
                float x1 = __shfl_sync(0xffffffffu, e3, srcLo);
                float y0 = __shfl_sync(0xffffffffu, e2, srcHi);
                float y1 = __shfl_sync(0xffffffffu, e3, srcHi);
                uint32_t pa[4];
                pa[0] = tf32r(odd ? u1 : u0);
                pa[1] = tf32r(odd ? x1 : x0);
                pa[2] = tf32r(odd ? w1 : w0);
                pa[3] = tf32r(odd ? y1 : y0);

                #pragma unroll
                for (int nn = 0; nn < 4; nn++)
                    mma8(of[mt][nn], pa, vw0[nn], vw1[nn]);
            }
        }
    }

    // ---- epilogue (sO/sL alias the KV buffers; safe after barrier) ----
    __syncthreads();
    float* sO = reinterpret_cast<float*>(sbuf);
    float* sL = reinterpret_cast<float*>(sbuf + QBLK * 34 * 4);

    #pragma unroll
    for (int mt = 0; mt < 2; mt++) {
        l[mt][0] += __shfl_xor_sync(0xffffffffu, l[mt][0], 1);
        l[mt][0] += __shfl_xor_sync(0xffffffffu, l[mt][0], 2);
        l[mt][1] += __shfl_xor_sync(0xffffffffu, l[mt][1], 1);
        l[mt][1] += __shfl_xor_sync(0xffffffffu, l[mt][1], 2);
    }

    if (w & 1) {
        #pragma unroll
        for (int mt = 0; mt < 2; mt++) {
            int r = m0 + mt * 16 + g;
            if (t == 0) { sL[r] = l[mt][0]; sL[r + 8] = l[mt][1]; }
            #pragma unroll
            for (int nn = 0; nn < 4; nn++) {
                *reinterpret_cast<float2*>(&sO[r * 34 + 8 * nn + 2 * t]) =
                    make_float2(of[mt][nn][0], of[mt][nn][1]);
                *reinterpret_cast<float2*>(&sO[(r + 8) * 34 + 8 * nn + 2 * t]) =
                    make_float2(of[mt][nn][2], of[mt][nn][3]);
            }
        }
    }
    __syncthreads();
    if (!(w & 1)) {
        #pragma unroll
        for (int mt = 0; mt < 2; mt++) {
            int r = m0 + mt * 16 + g;
            float L0 = l[mt][0] + sL[r];
            float L1 = l[mt][1] + sL[r + 8];
            float i0 = 1.0f / L0, i1 = 1.0f / L1;
            #pragma unroll
            for (int nn = 0; nn < 4; nn++) {
                float2 a = *reinterpret_cast<const float2*>(&sO[r * 34 + 8 * nn + 2 * t]);
                float2 b = *reinterpret_cast<const float2*>(&sO[(r + 8) * 34 + 8 * nn + 2 * t]);
                *reinterpret_cast<float2*>(
                    &xcat[(size_t)(q0 + r) * HID + h * HD + 8 * nn + 2 * t]) =
                    make_float2((of[mt][nn][0] + a.x) * i0, (of[mt][nn][1] + a.y) * i0);
                *reinterpret_cast<float2*>(
                    &xcat[(size_t)(q0 + r + 8) * HID + h * HD + 8 * nn + 2 * t]) =
                    make_float2((of[mt][nn][2] + b.x) * i1, (of[mt][nn][3] + b.y) * i1);
            }
        }
    }
}

// ---------------------------------------------------------------------------
extern "C" void kernel_launch(void* const* d_in, const int* in_sizes, int n_in,
                              void* d_out, int out_size)
{
    const float* x   = (const float*)d_in[0];
    const float* peQ = (const float*)d_in[1];
    const float* peK = (const float*)d_in[2];
    const float* WQ  = (const float*)d_in[4];
    const float* WK  = (const float*)d_in[5];
    const float* WV  = (const float*)d_in[6];
    const float* Qb  = (const float*)d_in[7];
    const float* Kb  = (const float*)d_in[8];
    const float* Vb  = (const float*)d_in[9];
    const float* lw  = (const float*)d_in[10];
    const float* lb  = (const float*)d_in[11];
    float* out = (float*)d_out;

    float *qp, *kp, *vp, *xc;
    cudaGetSymbolAddress((void**)&qp, g_Q);
    cudaGetSymbolAddress((void**)&kp, g_K);
    cudaGetSymbolAddress((void**)&vp, g_V);
    cudaGetSymbolAddress((void**)&xc, g_xcat);

    projqk_kernel<<<dim3(N_TOK / 128, HID / 64, 2), 256>>>(
        x, peQ, peK, WQ, WK, Qb, Kb, qp, kp);
    projv_tc_kernel<<<dim3(N_TOK / 64, HID / 64), 256>>>(x, WV, Vb, vp);
    attn_mma_kernel<<<dim3(N_TOK / QBLK, HEADS), 256>>>(qp, kp, vp, xc);
    final_tc_kernel<<<dim3(N_TOK / 64, HID / 64), 256>>>(xc, lw, lb, out);
}

// round 13
// speedup vs baseline: 1.3977x; 1.1188x over previous
#include <cuda_runtime.h>
#include <math_constants.h>
#include <cstdint>

#define N_TOK 4096
#define IN_DIM 256
#define HID 256
#define HEADS 8
#define HD 32
#define QBLK 128
#define KBLK 64
#define NITER (N_TOK / KBLK)
#define KSTR 36
#define VSTR 40
#define BSTR 72    // projqk/projv B-tile row stride (conflict-free: 8t+g)
#define BSTR2 73   // final B-tile row stride (breaks transposed-fill conflicts)

// attn SMEM layout (bytes): double-buffered [Ks | Vs] stages; epilogue aliases
#define KBYTES (KBLK * KSTR * 4)          // 9216
#define VBYTES (KBLK * VSTR * 4)          // 10240
#define STAGE_BYTES (KBYTES + VBYTES)     // 19456
#define SBUF_BYTES (2 * STAGE_BYTES)      // 38912

// 1/sqrt(256) * log2(e): exp(x*0.0625) == exp2(x*SC2Q)
#define SC2Q (0.0625f * 1.4426950408889634f)

// Scratch (static __device__ arrays — allocation-free per harness rules)
// g_Q holds tf32-rounded, SC2Q-pre-scaled Q bits; g_K/g_V hold tf32-rounded bits.
__device__ float g_Q[HEADS * N_TOK * HD];
__device__ float g_K[HEADS * N_TOK * HD];
__device__ float g_V[HEADS * N_TOK * HD];
__device__ float g_xcat[N_TOK * HID];

// ===========================================================================
__device__ __forceinline__ uint32_t tf32r(float x) {
    uint32_t u;
    asm("cvt.rna.tf32.f32 %0, %1;" : "=r"(u) : "f"(x));
    return u;
}
__device__ __forceinline__ void split2(float v, uint32_t& hi, uint32_t& lo) {
    hi = tf32r(v);
    lo = tf32r(v - __uint_as_float(hi));
}
__device__ __forceinline__ uint32_t smem_u32(const void* p) {
    uint32_t a;
    asm("{ .reg .u64 t; cvta.to.shared.u64 t, %1; cvt.u32.u64 %0, t; }" : "=r"(a) : "l"(p));
    return a;
}
__device__ __forceinline__ void cp16(uint32_t saddr, const void* gaddr) {
    asm volatile("cp.async.cg.shared.global [%0], [%1], 16;"
                 :: "r"(saddr), "l"(gaddr) : "memory");
}
#define CP_COMMIT() asm volatile("cp.async.commit_group;" ::: "memory")
#define CP_WAIT0()  asm volatile("cp.async.wait_group 0;" ::: "memory")

// K-row permutation within each 8-row group: slot 2t <- row t, slot 2t+1 <- row t+4.
// Makes the S-tile C-fragment land directly in P.V A-layout (no shuffles).
__device__ __forceinline__ int slotmap(int r) {
    return (r & ~7) | (((r & 3) << 1) | ((r & 7) >> 2));
}

// D += A * B   (m16n8k8, tf32 inputs as .b32, f32 accumulate)
__device__ __forceinline__ void mma8(float* d, const uint32_t* a,
                                     uint32_t b0, uint32_t b1) {
    asm volatile(
        "mma.sync.aligned.m16n8k8.row.col.f32.tf32.tf32.f32 "
        "{%0,%1,%2,%3}, {%4,%5,%6,%7}, {%8,%9}, {%0,%1,%2,%3};"
        : "+f"(d[0]), "+f"(d[1]), "+f"(d[2]), "+f"(d[3])
        : "r"(a[0]), "r"(a[1]), "r"(a[2]), "r"(a[3]), "r"(b0), "r"(b1));
}

// ---------------------------------------------------------------------------
// Q/K projection via tf32 mma.sync. Epilogue writes tf32-rounded bits
// (Q pre-scaled by SC2Q).
// ---------------------------------------------------------------------------
__global__ __launch_bounds__(256) void projqk_kernel(
    const float* __restrict__ x,
    const float* __restrict__ peQ, const float* __restrict__ peK,
    const float* __restrict__ WQ, const float* __restrict__ WK,
    const float* __restrict__ Qb, const float* __restrict__ Kb,
    float* __restrict__ outQ, float* __restrict__ outK)
{
    __shared__ uint32_t As[128 * 36];
    __shared__ uint32_t Bs[32 * BSTR];

    const float* pe   = blockIdx.z ? peK : peQ;
    const float* W    = blockIdx.z ? WK  : WQ;
    const float* bias = blockIdx.z ? Kb  : Qb;
    float* out        = blockIdx.z ? outK : outQ;
    const float osc   = blockIdx.z ? 1.0f : SC2Q;

    const int tid = threadIdx.x;
    const int w = tid >> 5, lane = tid & 31;
    const int g = lane >> 2, t = lane & 3;
    const int wm = w >> 1, wn = w & 1;
    const int m0 = blockIdx.x * 128;
    const int n0 = blockIdx.y * 64;

    float acc[2][4][4] = {};

    for (int k0 = 0; k0 < 1024; k0 += 32) {
        __syncthreads();
        #pragma unroll
        for (int i = 0; i < 4; i++) {
            int idx = tid + 256 * i;
            int row = idx >> 3;
            int col = (idx & 7) * 4;
            const float* src = (k0 < IN_DIM)
                ? &x[(size_t)(m0 + row) * IN_DIM + k0 + col]
                : &pe[(size_t)(m0 + row) * 768 + (k0 - IN_DIM) + col];
            float4 v = *reinterpret_cast<const float4*>(src);
            *reinterpret_cast<uint4*>(&As[row * 36 + col]) =
                make_uint4(tf32r(v.x), tf32r(v.y), tf32r(v.z), tf32r(v.w));
        }
        #pragma unroll
        for (int i = 0; i < 2; i++) {
            int idx = tid + 256 * i;
            int kk = idx >> 4;
            int c = (idx & 15) * 4;
            int col = n0 + c;
            float4 v = *reinterpret_cast<const float4*>(
                &W[((size_t)(col >> 5) * 1024 + k0 + kk) * HD + (col & 31)]);
            *reinterpret_cast<uint4*>(&Bs[kk * BSTR + c]) =
                make_uint4(tf32r(v.x), tf32r(v.y), tf32r(v.z), tf32r(v.w));
        }
        __syncthreads();

        #pragma unroll
        for (int ks = 0; ks < 4; ks++) {
            uint32_t af[2][4];
            #pragma unroll
            for (int mt = 0; mt < 2; mt++) {
                int rb = (wm * 32 + mt * 16) * 36 + ks * 8 + t;
                af[mt][0] = As[rb + g * 36];
                af[mt][1] = As[rb + (g + 8) * 36];
                af[mt][2] = As[rb + g * 36 + 4];
                af[mt][3] = As[rb + (g + 8) * 36 + 4];
            }
            #pragma unroll
            for (int nt = 0; nt < 4; nt++) {
                uint32_t b0 = Bs[(ks * 8 + t) * BSTR + wn * 32 + nt * 8 + g];
                uint32_t b1 = Bs[(ks * 8 + t + 4) * BSTR + wn * 32 + nt * 8 + g];
                mma8(acc[0][nt], af[0], b0, b1);
                mma8(acc[1][nt], af[1], b0, b1);
            }
        }
    }

    #pragma unroll
    for (int mt = 0; mt < 2; mt++) {
        int r0 = m0 + wm * 32 + mt * 16 + g;
        #pragma unroll
        for (int nt = 0; nt < 4; nt++) {
            int col = n0 + wn * 32 + nt * 8 + 2 * t;
            int hh = col >> 5, inner = col & 31;
            float bv0 = bias[col], bv1 = bias[col + 1];
            *reinterpret_cast<float2*>(
                &out[((size_t)hh * N_TOK + r0) * HD + inner]) =
                make_float2(__uint_as_float(tf32r((acc[mt][nt][0] + bv0) * osc)),
                            __uint_as_float(tf32r((acc[mt][nt][1] + bv1) * osc)));
            *reinterpret_cast<float2*>(
                &out[((size_t)hh * N_TOK + r0 + 8) * HD + inner]) =
                make_float2(__uint_as_float(tf32r((acc[mt][nt][2] + bv0) * osc)),
                            __uint_as_float(tf32r((acc[mt][nt][3] + bv1) * osc)));
        }
    }
}

// ---------------------------------------------------------------------------
// V projection, split-tf32; writes tf32-rounded bits.
// ---------------------------------------------------------------------------
__global__ __launch_bounds__(256) void projv_tc_kernel(
    const float* __restrict__ x, const float* __restrict__ W,
    const float* __restrict__ bias, float* __restrict__ out)
{
    __shared__ uint32_t Ah[64 * 36], Al[64 * 36];
    __shared__ uint32_t Bh[32 * BSTR], Bl[32 * BSTR];

    const int tid = threadIdx.x;
    const int w = tid >> 5, lane = tid & 31;
    const int g = lane >> 2, t = lane & 3;
    const int wm = w & 1, wn = w >> 1;
    const int m0 = blockIdx.x * 64;
    const int n0 = blockIdx.y * 64;

    float acc[2][2][4] = {};

    for (int k0 = 0; k0 < 256; k0 += 32) {
        __syncthreads();
        #pragma unroll
        for (int i = 0; i < 2; i++) {
            int idx = tid + 256 * i;
            int row = idx >> 3;
            int col = (idx & 7) * 4;
            float4 v = *reinterpret_cast<const float4*>(
                &x[(size_t)(m0 + row) * IN_DIM + k0 + col]);
            uint4 h, l;
            split2(v.x, h.x, l.x); split2(v.y, h.y, l.y);
            split2(v.z, h.z, l.z); split2(v.w, h.w, l.w);
            *reinterpret_cast<uint4*>(&Ah[row * 36 + col]) = h;
            *reinterpret_cast<uint4*>(&Al[row * 36 + col]) = l;
        }
        #pragma unroll
        for (int i = 0; i < 2; i++) {
            int idx = tid + 256 * i;
            int kk = idx >> 4;
            int c = (idx & 15) * 4;
            int col = n0 + c;
            float4 v = *reinterpret_cast<const float4*>(
                &W[((size_t)(col >> 5) * 256 + k0 + kk) * HD + (col & 31)]);
            uint4 h, l;
            split2(v.x, h.x, l.x); split2(v.y, h.y, l.y);
            split2(v.z, h.z, l.z); split2(v.w, h.w, l.w);
            *reinterpret_cast<uint4*>(&Bh[kk * BSTR + c]) = h;
            *reinterpret_cast<uint4*>(&Bl[kk * BSTR + c]) = l;
        }
        __syncthreads();

        #pragma unroll
        for (int ks = 0; ks < 4; ks++) {
            uint32_t afh[2][4], afl[2][4];
            #pragma unroll
            for (int mt = 0; mt < 2; mt++) {
                int rb = (wm * 32 + mt * 16) * 36 + ks * 8 + t;
                afh[mt][0] = Ah[rb + g * 36];
                afh[mt][1] = Ah[rb + (g + 8) * 36];
                afh[mt][2] = Ah[rb + g * 36 + 4];
                afh[mt][3] = Ah[rb + (g + 8) * 36 + 4];
                afl[mt][0] = Al[rb + g * 36];
                afl[mt][1] = Al[rb + (g + 8) * 36];
                afl[mt][2] = Al[rb + g * 36 + 4];
                afl[mt][3] = Al[rb + (g + 8) * 36 + 4];
            }
            #pragma unroll
            for (int nt = 0; nt < 2; nt++) {
                int cb = wn * 16 + nt * 8 + g;
                uint32_t b0h = Bh[(ks * 8 + t) * BSTR + cb];
                uint32_t b1h = Bh[(ks * 8 + t + 4) * BSTR + cb];
                uint32_t b0l = Bl[(ks * 8 + t) * BSTR + cb];
                uint32_t b1l = Bl[(ks * 8 + t + 4) * BSTR + cb];
                #pragma unroll
                for (int mt = 0; mt < 2; mt++) {
                    mma8(acc[mt][nt], afh[mt], b0h, b1h);
                    mma8(acc[mt][nt], afh[mt], b0l, b1l);
                    mma8(acc[mt][nt], afl[mt], b0h, b1h);
                }
            }
        }
    }

    #pragma unroll
    for (int mt = 0; mt < 2; mt++) {
        int r0 = m0 + wm * 32 + mt * 16 + g;
        #pragma unroll
        for (int nt = 0; nt < 2; nt++) {
            int col = n0 + wn * 16 + nt * 8 + 2 * t;
            int hh = col >> 5, inner = col & 31;
            float bv0 = bias[col], bv1 = bias[col + 1];
            *reinterpret_cast<float2*>(
                &out[((size_t)hh * N_TOK + r0) * HD + inner]) =
                make_float2(__uint_as_float(tf32r(acc[mt][nt][0] + bv0)),
                            __uint_as_float(tf32r(acc[mt][nt][1] + bv1)));
            *reinterpret_cast<float2*>(
                &out[((size_t)hh * N_TOK + r0 + 8) * HD + inner]) =
                make_float2(__uint_as_float(tf32r(acc[mt][nt][2] + bv0)),
                            __uint_as_float(tf32r(acc[mt][nt][3] + bv1)));
        }
    }
}

// ---------------------------------------------------------------------------
// Final linear, split-tf32: out = xcat @ lw^T + lb
// ---------------------------------------------------------------------------
__global__ __launch_bounds__(256) void final_tc_kernel(
    const float* __restrict__ xcat, const float* __restrict__ lw,
    const float* __restrict__ lb, float* __restrict__ out)
{
    __shared__ uint32_t Ah[64 * 36], Al[64 * 36];
    __shared__ uint32_t Bh[32 * BSTR2], Bl[32 * BSTR2];

    const int tid = threadIdx.x;
    const int w = tid >> 5, lane = tid & 31;
    const int g = lane >> 2, t = lane & 3;
    const int wm = w & 1, wn = w >> 1;
    const int m0 = blockIdx.x * 64;
    const int n0 = blockIdx.y * 64;

    float acc[2][2][4] = {};

    for (int k0 = 0; k0 < 256; k0 += 32) {
        __syncthreads();
        #pragma unroll
        for (int i = 0; i < 2; i++) {
            int idx = tid + 256 * i;
            int row = idx >> 3;
            int col = (idx & 7) * 4;
            float4 v = *reinterpret_cast<const float4*>(
                &xcat[(size_t)(m0 + row) * HID + k0 + col]);
            uint4 h, l;
            split2(v.x, h.x, l.x); split2(v.y, h.y, l.y);
            split2(v.z, h.z, l.z); split2(v.w, h.w, l.w);
            *reinterpret_cast<uint4*>(&Ah[row * 36 + col]) = h;
            *reinterpret_cast<uint4*>(&Al[row * 36 + col]) = l;
        }
        #pragma unroll
        for (int i = 0; i < 2; i++) {
            int idx = tid + 256 * i;
            int c = idx >> 3;
            int kq = (idx & 7) * 4;
            float4 v = *reinterpret_cast<const float4*>(
                &lw[(size_t)(n0 + c) * HID + k0 + kq]);
            uint32_t h0, l0v, h1, l1v, h2, l2v, h3, l3v;
            split2(v.x, h0, l0v); split2(v.y, h1, l1v);
            split2(v.z, h2, l2v); split2(v.w, h3, l3v);
            Bh[(kq + 0) * BSTR2 + c] = h0;  Bl[(kq + 0) * BSTR2 + c] = l0v;
            Bh[(kq + 1) * BSTR2 + c] = h1;  Bl[(kq + 1) * BSTR2 + c] = l1v;
            Bh[(kq + 2) * BSTR2 + c] = h2;  Bl[(kq + 2) * BSTR2 + c] = l2v;
            Bh[(kq + 3) * BSTR2 + c] = h3;  Bl[(kq + 3) * BSTR2 + c] = l3v;
        }
        __syncthreads();

        #pragma unroll
        for (int ks = 0; ks < 4; ks++) {
            uint32_t afh[2][4], afl[2][4];
            #pragma unroll
            for (int mt = 0; mt < 2; mt++) {
                int rb = (wm * 32 + mt * 16) * 36 + ks * 8 + t;
                afh[mt][0] = Ah[rb + g * 36];
                afh[mt][1] = Ah[rb + (g + 8) * 36];
                afh[mt][2] = Ah[rb + g * 36 + 4];
                afh[mt][3] = Ah[rb + (g + 8) * 36 + 4];
                afl[mt][0] = Al[rb + g * 36];
                afl[mt][1] = Al[rb + (g + 8) * 36];
                afl[mt][2] = Al[rb + g * 36 + 4];
                afl[mt][3] = Al[rb + (g + 8) * 36 + 4];
            }
            #pragma unroll
            for (int nt = 0; nt < 2; nt++) {
                int cb = wn * 16 + nt * 8 + g;
                uint32_t b0h = Bh[(ks * 8 + t) * BSTR2 + cb];
                uint32_t b1h = Bh[(ks * 8 + t + 4) * BSTR2 + cb];
                uint32_t b0l = Bl[(ks * 8 + t) * BSTR2 + cb];
                uint32_t b1l = Bl[(ks * 8 + t + 4) * BSTR2 + cb];
                #pragma unroll
                for (int mt = 0; mt < 2; mt++) {
                    mma8(acc[mt][nt], afh[mt], b0h, b1h);
                    mma8(acc[mt][nt], afh[mt], b0l, b1l);
                    mma8(acc[mt][nt], afl[mt], b0h, b1h);
                }
            }
        }
    }

    #pragma unroll
    for (int mt = 0; mt < 2; mt++) {
        int r0 = m0 + wm * 32 + mt * 16 + g;
        #pragma unroll
        for (int nt = 0; nt < 2; nt++) {
            int col = n0 + wn * 16 + nt * 8 + 2 * t;
            float bv0 = lb[col], bv1 = lb[col + 1];
            *reinterpret_cast<float2*>(&out[(size_t)r0 * HID + col]) =
                make_float2(acc[mt][nt][0] + bv0, acc[mt][nt][1] + bv1);
            *reinterpret_cast<float2*>(&out[(size_t)(r0 + 8) * HID + col]) =
                make_float2(acc[mt][nt][2] + bv0, acc[mt][nt][3] + bv1);
        }
    }
}

// ---------------------------------------------------------------------------
// Flash attention: tf32 mma.sync, m-doubled, cp.async double-buffered KV,
// K rows stored group-permuted so the S C-fragment IS the P.V A-fragment
// (shuffle-free softmax->PV handoff; bit-identical math).
// Grid (N/128, HEADS); block 256 (8 warps).
// ---------------------------------------------------------------------------
__global__ __launch_bounds__(256) void attn_mma_kernel(
    const float* __restrict__ Qg, const float* __restrict__ Kg,
    const float* __restrict__ Vg, float* __restrict__ xcat)
{
    __shared__ __align__(16) char sbuf[SBUF_BYTES];
    const uint32_t sb = smem_u32(sbuf);

    const int tid = threadIdx.x;
    const int w = tid >> 5;
    const int lane = tid & 31;
    const int g = lane >> 2;
    const int t = lane & 3;
    const int h = blockIdx.y;
    const int q0 = blockIdx.x * QBLK;
    const int wm = w >> 1;
    const int m0 = wm * 32;
    const int c0 = (w & 1) * 32;

    const float* Qh = Qg + (size_t)h * N_TOK * HD;
    const float* Kh = Kg + (size_t)h * N_TOK * HD;
    const float* Vh = Vg + (size_t)h * N_TOK * HD;

    // ---- Q fragments: pre-scaled + pre-rounded bits, direct load ----
    uint32_t qf[2][4][4];
    #pragma unroll
    for (int mt = 0; mt < 2; mt++) {
        const float* qr0 = Qh + (size_t)(q0 + m0 + mt * 16 + g) * HD;
        const float* qr1 = qr0 + 8 * HD;
        #pragma unroll
        for (int s = 0; s < 4; s++) {
            qf[mt][s][0] = __float_as_uint(qr0[8 * s + t]);
            qf[mt][s][1] = __float_as_uint(qr1[8 * s + t]);
            qf[mt][s][2] = __float_as_uint(qr0[8 * s + t + 4]);
            qf[mt][s][3] = __float_as_uint(qr1[8 * s + t + 4]);
        }
    }

    float of[2][4][4] = {};
    float l[2][2] = {};

    // ---- cp.async fill geometry: each thread copies 4x16B per tile ----
    const int frow = tid >> 3;            // 0..31
    const int fb = (tid & 7) * 16;        // byte offset within 128B row
    const int ks0 = slotmap(frow);        // permuted K slot for row frow
    const int ks1 = slotmap(frow + 32);   // permuted K slot for row frow+32

    // preload tile 0 into stage 0
    {
        const char* kg = (const char*)(Kh + (size_t)frow * HD) + fb;
        const char* vg = (const char*)(Vh + (size_t)frow * HD) + fb;
        cp16(sb + ks0 * (KSTR * 4) + fb, kg);
        cp16(sb + ks1 * (KSTR * 4) + fb, kg + 32 * HD * 4);
        cp16(sb + KBYTES + frow * (VSTR * 4) + fb, vg);
        cp16(sb + KBYTES + (frow + 32) * (VSTR * 4) + fb, vg + 32 * HD * 4);
        CP_COMMIT();
    }

    for (int kb = 0; kb < NITER; kb++) {
        CP_WAIT0();
        __syncthreads();   // tile kb visible to all; all warps done with kb-1

        const int stage = kb & 1;
        if (kb + 1 < NITER) {
            const uint32_t nb = sb + (stage ^ 1) * STAGE_BYTES;
            const char* kg = (const char*)(Kh + (size_t)((kb + 1) * KBLK + frow) * HD) + fb;
            const char* vg = (const char*)(Vh + (size_t)((kb + 1) * KBLK + frow) * HD) + fb;
            cp16(nb + ks0 * (KSTR * 4) + fb, kg);
            cp16(nb + ks1 * (KSTR * 4) + fb, kg + 32 * HD * 4);
            cp16(nb + KBYTES + frow * (VSTR * 4) + fb, vg);
            cp16(nb + KBYTES + (frow + 32) * (VSTR * 4) + fb, vg + 32 * HD * 4);
            CP_COMMIT();
        }

        const uint32_t* Ksp = reinterpret_cast<const uint32_t*>(sbuf + stage * STAGE_BYTES);
        const uint32_t* Vsp = reinterpret_cast<const uint32_t*>(sbuf + stage * STAGE_BYTES + KBYTES);

        #pragma unroll
        for (int j = 0; j < 4; j++) {
            const uint32_t* kbp = &Ksp[(c0 + 8 * j + g) * KSTR + t];
            uint32_t kw[8];
            #pragma unroll
            for (int s = 0; s < 4; s++) {
                kw[2 * s]     = kbp[8 * s];
                kw[2 * s + 1] = kbp[8 * s + 4];
            }
            float sf[2][4] = {};
            #pragma unroll
            for (int mt = 0; mt < 2; mt++)
                #pragma unroll
                for (int s = 0; s < 4; s++)
                    mma8(sf[mt], qf[mt][s], kw[2 * s], kw[2 * s + 1]);

            const uint32_t* vb0 = &Vsp[(c0 + 8 * j + t) * VSTR + g];
            const uint32_t* vb1 = vb0 + 4 * VSTR;
            uint32_t vw0[4], vw1[4];
            #pragma unroll
            for (int nn = 0; nn < 4; nn++) { vw0[nn] = vb0[8 * nn]; vw1[nn] = vb1[8 * nn]; }

            #pragma unroll
            for (int mt = 0; mt < 2; mt++) {
                // C-fragment (with permuted K columns):
                //   sf[0]=P[g][t]  sf[1]=P[g][t+4]  sf[2]=P[g+8][t]  sf[3]=P[g+8][t+4]
                float e0 = exp2f(sf[mt][0]);
                float e1 = exp2f(sf[mt][1]);
                float e2 = exp2f(sf[mt][2]);
                float e3 = exp2f(sf[mt][3]);
                l[mt][0] += e0 + e1;
                l[mt][1] += e2 + e3;

                // A-layout directly: a0=(g,t) a1=(g+8,t) a2=(g,t+4) a3=(g+8,t+4)
                uint32_t pa[4];
                pa[0] = tf32r(e0);
                pa[1] = tf32r(e2);
                pa[2] = tf32r(e1);
                pa[3] = tf32r(e3);

                #pragma unroll
                for (int nn = 0; nn < 4; nn++)
                    mma8(of[mt][nn], pa, vw0[nn], vw1[nn]);
            }
        }
    }

    // ---- epilogue (sO/sL alias the KV buffers; safe after barrier) ----
    __syncthreads();
    float* sO = reinterpret_cast<float*>(sbuf);
    float* sL = reinterpret_cast<float*>(sbuf + QBLK * 34 * 4);

    #pragma unroll
    for (int mt = 0; mt < 2; mt++) {
        l[mt][0] += __shfl_xor_sync(0xffffffffu, l[mt][0], 1);
        l[mt][0] += __shfl_xor_sync(0xffffffffu, l[mt][0], 2);
        l[mt][1] += __shfl_xor_sync(0xffffffffu, l[mt][1], 1);
        l[mt][1] += __shfl_xor_sync(0xffffffffu, l[mt][1], 2);
    }

    if (w & 1) {
        #pragma unroll
        for (int mt = 0; mt < 2; mt++) {
            int r = m0 + mt * 16 + g;
            if (t == 0) { sL[r] = l[mt][0]; sL[r + 8] = l[mt][1]; }
            #pragma unroll
            for (int nn = 0; nn < 4; nn++) {
                *reinterpret_cast<float2*>(&sO[r * 34 + 8 * nn + 2 * t]) =
                    make_float2(of[mt][nn][0], of[mt][nn][1]);
                *reinterpret_cast<float2*>(&sO[(r + 8) * 34 + 8 * nn + 2 * t]) =
                    make_float2(of[mt][nn][2], of[mt][nn][3]);
            }
        }
    }
    __syncthreads();
    if (!(w & 1)) {
        #pragma unroll
        for (int mt = 0; mt < 2; mt++) {
            int r = m0 + mt * 16 + g;
            float L0 = l[mt][0] + sL[r];
            float L1 = l[mt][1] + sL[r + 8];
            float i0 = 1.0f / L0, i1 = 1.0f / L1;
            #pragma unroll
            for (int nn = 0; nn < 4; nn++) {
                float2 a = *reinterpret_cast<const float2*>(&sO[r * 34 + 8 * nn + 2 * t]);
                float2 b = *reinterpret_cast<const float2*>(&sO[(r + 8) * 34 + 8 * nn + 2 * t]);
                *reinterpret_cast<float2*>(
                    &xcat[(size_t)(q0 + r) * HID + h * HD + 8 * nn + 2 * t]) =
                    make_float2((of[mt][nn][0] + a.x) * i0, (of[mt][nn][1] + a.y) * i0);
                *reinterpret_cast<float2*>(
                    &xcat[(size_t)(q0 + r + 8) * HID + h * HD + 8 * nn + 2 * t]) =
                    make_float2((of[mt][nn][2] + b.x) * i1, (of[mt][nn][3] + b.y) * i1);
            }
        }
    }
}

// ---------------------------------------------------------------------------
extern "C" void kernel_launch(void* const* d_in, const int* in_sizes, int n_in,
                              void* d_out, int out_size)
{
    const float* x   = (const float*)d_in[0];
    const float* peQ = (const float*)d_in[1];
    const float* peK = (const float*)d_in[2];
    const float* WQ  = (const float*)d_in[4];
    const float* WK  = (const float*)d_in[5];
    const float* WV  = (const float*)d_in[6];
    const float* Qb  = (const float*)d_in[7];
    const float* Kb  = (const float*)d_in[8];
    const float* Vb  = (const float*)d_in[9];
    const float* lw  = (const float*)d_in[10];
    const float* lb  = (const float*)d_in[11];
    float* out = (float*)d_out;

    float *qp, *kp, *vp, *xc;
    cudaGetSymbolAddress((void**)&qp, g_Q);
    cudaGetSymbolAddress((void**)&kp, g_K);
    cudaGetSymbolAddress((void**)&vp, g_V);
    cudaGetSymbolAddress((void**)&xc, g_xcat);

    projqk_kernel<<<dim3(N_TOK / 128, HID / 64, 2), 256>>>(
        x, peQ, peK, WQ, WK, Qb, Kb, qp, kp);
    projv_tc_kernel<<<dim3(N_TOK / 64, HID / 64), 256>>>(x, WV, Vb, vp);
    attn_mma_kernel<<<dim3(N_TOK / QBLK, HEADS), 256>>>(qp, kp, vp, xc);
    final_tc_kernel<<<dim3(N_TOK / 64, HID / 64), 256>>>(xc, lw, lb, out);
}

// round 14
// speedup vs baseline: 1.4118x; 1.0101x over previous
#include <cuda_runtime.h>
#include <math_constants.h>
#include <cstdint>

#define N_TOK 4096
#define IN_DIM 256
#define HID 256
#define HEADS 8
#define HD 32
#define QBLK 128
#define KBLK 64
#define NITER (N_TOK / KBLK)
#define KSTR 40    // K tile row stride (words); LDS.64 idx 4g+t conflict-free
#define DVS 72     // V double-row stride (words); LDS.64 idx 4t+g conflict-free
#define BSTR 72    // projqk/projv B-tile row stride (conflict-free: 8t+g)
#define BSTR2 73   // final B-tile row stride (breaks transposed-fill conflicts)

// attn SMEM layout (bytes): double-buffered [Ks | Vs] stages; epilogue aliases
#define KBYTES (KBLK * KSTR * 4)          // 10240
#define VBYTES (32 * DVS * 4)             // 9216 (32 double-rows x 72 words)
#define STAGE_BYTES (KBYTES + VBYTES)     // 19456
#define SBUF_BYTES (2 * STAGE_BYTES)      // 38912

// 1/sqrt(256) * log2(e): exp(x*0.0625) == exp2(x*SC2Q)
#define SC2Q (0.0625f * 1.4426950408889634f)

// Scratch (static __device__ arrays — allocation-free per harness rules)
// g_Q: tf32-rounded, SC2Q-pre-scaled Q (row-linear).
// g_K: tf32-rounded K, columns pair-permuted within 8-groups ([0,4,1,5,2,6,3,7]).
// g_V: tf32-rounded V in double-row layout: ((h*512+jg)*4+t)*64 + 2c + s,
//      s=0 -> row 8jg+t, s=1 -> row 8jg+t+4.
__device__ float g_Q[HEADS * N_TOK * HD];
__device__ float g_K[HEADS * N_TOK * HD];
__device__ float g_V[HEADS * N_TOK * HD];
__device__ float g_xcat[N_TOK * HID];

// ===========================================================================
__device__ __forceinline__ uint32_t tf32r(float x) {
    uint32_t u;
    asm("cvt.rna.tf32.f32 %0, %1;" : "=r"(u) : "f"(x));
    return u;
}
__device__ __forceinline__ void split2(float v, uint32_t& hi, uint32_t& lo) {
    hi = tf32r(v);
    lo = tf32r(v - __uint_as_float(hi));
}
__device__ __forceinline__ uint32_t smem_u32(const void* p) {
    uint32_t a;
    asm("{ .reg .u64 t; cvta.to.shared.u64 t, %1; cvt.u32.u64 %0, t; }" : "=r"(a) : "l"(p));
    return a;
}
__device__ __forceinline__ void cp16(uint32_t saddr, const void* gaddr) {
    asm volatile("cp.async.cg.shared.global [%0], [%1], 16;"
                 :: "r"(saddr), "l"(gaddr) : "memory");
}
#define CP_COMMIT() asm volatile("cp.async.commit_group;" ::: "memory")
#define CP_WAIT0()  asm volatile("cp.async.wait_group 0;" ::: "memory")

// pair-permutation within an 8-element group: pos 2t <- elem t, 2t+1 <- elem t+4
__device__ __forceinline__ int slotmap(int r) {
    return (r & ~7) | (((r & 3) << 1) | ((r & 7) >> 2));
}

// D += A * B   (m16n8k8, tf32 inputs as .b32, f32 accumulate)
__device__ __forceinline__ void mma8(float* d, const uint32_t* a,
                                     uint32_t b0, uint32_t b1) {
    asm volatile(
        "mma.sync.aligned.m16n8k8.row.col.f32.tf32.tf32.f32 "
        "{%0,%1,%2,%3}, {%4,%5,%6,%7}, {%8,%9}, {%0,%1,%2,%3};"
        : "+f"(d[0]), "+f"(d[1]), "+f"(d[2]), "+f"(d[3])
        : "r"(a[0]), "r"(a[1]), "r"(a[2]), "r"(a[3]), "r"(b0), "r"(b1));
}

// ---------------------------------------------------------------------------
// Q/K projection via tf32 mma.sync. Q: pre-scaled+rounded, row-linear.
// K: rounded, columns pair-permuted within each 8-group (for LDS.64 in attn).
// ---------------------------------------------------------------------------
__global__ __launch_bounds__(256) void projqk_kernel(
    const float* __restrict__ x,
    const float* __restrict__ peQ, const float* __restrict__ peK,
    const float* __restrict__ WQ, const float* __restrict__ WK,
    const float* __restrict__ Qb, const float* __restrict__ Kb,
    float* __restrict__ outQ, float* __restrict__ outK)
{
    __shared__ uint32_t As[128 * 36];
    __shared__ uint32_t Bs[32 * BSTR];

    const float* pe   = blockIdx.z ? peK : peQ;
    const float* W    = blockIdx.z ? WK  : WQ;
    const float* bias = blockIdx.z ? Kb  : Qb;
    float* out        = blockIdx.z ? outK : outQ;
    const float osc   = blockIdx.z ? 1.0f : SC2Q;
    const int isK     = blockIdx.z;

    const int tid = threadIdx.x;
    const int w = tid >> 5, lane = tid & 31;
    const int g = lane >> 2, t = lane & 3;
    const int wm = w >> 1, wn = w & 1;
    const int m0 = blockIdx.x * 128;
    const int n0 = blockIdx.y * 64;

    float acc[2][4][4] = {};

    for (int k0 = 0; k0 < 1024; k0 += 32) {
        __syncthreads();
        #pragma unroll
        for (int i = 0; i < 4; i++) {
            int idx = tid + 256 * i;
            int row = idx >> 3;
            int col = (idx & 7) * 4;
            const float* src = (k0 < IN_DIM)
                ? &x[(size_t)(m0 + row) * IN_DIM + k0 + col]
                : &pe[(size_t)(m0 + row) * 768 + (k0 - IN_DIM) + col];
            float4 v = *reinterpret_cast<const float4*>(src);
            *reinterpret_cast<uint4*>(&As[row * 36 + col]) =
                make_uint4(tf32r(v.x), tf32r(v.y), tf32r(v.z), tf32r(v.w));
        }
        #pragma unroll
        for (int i = 0; i < 2; i++) {
            int idx = tid + 256 * i;
            int kk = idx >> 4;
            int c = (idx & 15) * 4;
            int col = n0 + c;
            float4 v = *reinterpret_cast<const float4*>(
                &W[((size_t)(col >> 5) * 1024 + k0 + kk) * HD + (col & 31)]);
            *reinterpret_cast<uint4*>(&Bs[kk * BSTR + c]) =
                make_uint4(tf32r(v.x), tf32r(v.y), tf32r(v.z), tf32r(v.w));
        }
        __syncthreads();

        #pragma unroll
        for (int ks = 0; ks < 4; ks++) {
            uint32_t af[2][4];
            #pragma unroll
            for (int mt = 0; mt < 2; mt++) {
                int rb = (wm * 32 + mt * 16) * 36 + ks * 8 + t;
                af[mt][0] = As[rb + g * 36];
                af[mt][1] = As[rb + (g + 8) * 36];
                af[mt][2] = As[rb + g * 36 + 4];
                af[mt][3] = As[rb + (g + 8) * 36 + 4];
            }
            #pragma unroll
            for (int nt = 0; nt < 4; nt++) {
                uint32_t b0 = Bs[(ks * 8 + t) * BSTR + wn * 32 + nt * 8 + g];
                uint32_t b1 = Bs[(ks * 8 + t + 4) * BSTR + wn * 32 + nt * 8 + g];
                mma8(acc[0][nt], af[0], b0, b1);
                mma8(acc[1][nt], af[1], b0, b1);
            }
        }
    }

    #pragma unroll
    for (int mt = 0; mt < 2; mt++) {
        int r0 = m0 + wm * 32 + mt * 16 + g;
        #pragma unroll
        for (int nt = 0; nt < 4; nt++) {
            int col = n0 + wn * 32 + nt * 8 + 2 * t;
            int hh = col >> 5, inner = col & 31;
            float bv0 = bias[col], bv1 = bias[col + 1];
            float z0 = __uint_as_float(tf32r((acc[mt][nt][0] + bv0) * osc));
            float z1 = __uint_as_float(tf32r((acc[mt][nt][1] + bv1) * osc));
            float z2 = __uint_as_float(tf32r((acc[mt][nt][2] + bv0) * osc));
            float z3 = __uint_as_float(tf32r((acc[mt][nt][3] + bv1) * osc));
            if (isK) {
                int w0 = slotmap(inner), w1 = slotmap(inner + 1);
                float* o0 = &out[((size_t)hh * N_TOK + r0) * HD];
                float* o1 = &out[((size_t)hh * N_TOK + r0 + 8) * HD];
                o0[w0] = z0; o0[w1] = z1;
                o1[w0] = z2; o1[w1] = z3;
            } else {
                *reinterpret_cast<float2*>(
                    &out[((size_t)hh * N_TOK + r0) * HD + inner]) = make_float2(z0, z1);
                *reinterpret_cast<float2*>(
                    &out[((size_t)hh * N_TOK + r0 + 8) * HD + inner]) = make_float2(z2, z3);
            }
        }
    }
}

// ---------------------------------------------------------------------------
// V projection, split-tf32. Epilogue writes V in the attn double-row layout:
//   elem (h, r, c) -> ((h*512 + r/8)*4 + (r%8)&3)*64 + 2c + ((r%8)>>2)
// ---------------------------------------------------------------------------
__global__ __launch_bounds__(256) void projv_tc_kernel(
    const float* __restrict__ x, const float* __restrict__ W,
    const float* __restrict__ bias, float* __restrict__ out)
{
    __shared__ uint32_t Ah[64 * 36], Al[64 * 36];
    __shared__ uint32_t Bh[32 * BSTR], Bl[32 * BSTR];

    const int tid = threadIdx.x;
    const int w = tid >> 5, lane = tid & 31;
    const int g = lane >> 2, t = lane & 3;
    const int wm = w & 1, wn = w >> 1;
    const int m0 = blockIdx.x * 64;
    const int n0 = blockIdx.y * 64;

    float acc[2][2][4] = {};

    for (int k0 = 0; k0 < 256; k0 += 32) {
        __syncthreads();
        #pragma unroll
        for (int i = 0; i < 2; i++) {
            int idx = tid + 256 * i;
            int row = idx >> 3;
            int col = (idx & 7) * 4;
            float4 v = *reinterpret_cast<const float4*>(
                &x[(size_t)(m0 + row) * IN_DIM + k0 + col]);
            uint4 h, l;
            split2(v.x, h.x, l.x); split2(v.y, h.y, l.y);
            split2(v.z, h.z, l.z); split2(v.w, h.w, l.w);
            *reinterpret_cast<uint4*>(&Ah[row * 36 + col]) = h;
            *reinterpret_cast<uint4*>(&Al[row * 36 + col]) = l;
        }
        #pragma unroll
        for (int i = 0; i < 2; i++) {
            int idx = tid + 256 * i;
            int kk = idx >> 4;
            int c = (idx & 15) * 4;
            int col = n0 + c;
            float4 v = *reinterpret_cast<const float4*>(
                &W[((size_t)(col >> 5) * 256 + k0 + kk) * HD + (col & 31)]);
            uint4 h, l;
            split2(v.x, h.x, l.x); split2(v.y, h.y, l.y);
            split2(v.z, h.z, l.z); split2(v.w, h.w, l.w);
            *reinterpret_cast<uint4*>(&Bh[kk * BSTR + c]) = h;
            *reinterpret_cast<uint4*>(&Bl[kk * BSTR + c]) = l;
        }
        __syncthreads();

        #pragma unroll
        for (int ks = 0; ks < 4; ks++) {
            uint32_t afh[2][4], afl[2][4];
            #pragma unroll
            for (int mt = 0; mt < 2; mt++) {
                int rb = (wm * 32 + mt * 16) * 36 + ks * 8 + t;
                afh[mt][0] = Ah[rb + g * 36];
                afh[mt][1] = Ah[rb + (g + 8) * 36];
                afh[mt][2] = Ah[rb + g * 36 + 4];
                afh[mt][3] = Ah[rb + (g + 8) * 36 + 4];
                afl[mt][0] = Al[rb + g * 36];
                afl[mt][1] = Al[rb + (g + 8) * 36];
                afl[mt][2] = Al[rb + g * 36 + 4];
                afl[mt][3] = Al[rb + (g + 8) * 36 + 4];
            }
            #pragma unroll
            for (int nt = 0; nt < 2; nt++) {
                int cb = wn * 16 + nt * 8 + g;
                uint32_t b0h = Bh[(ks * 8 + t) * BSTR + cb];
                uint32_t b1h = Bh[(ks * 8 + t + 4) * BSTR + cb];
                uint32_t b0l = Bl[(ks * 8 + t) * BSTR + cb];
                uint32_t b1l = Bl[(ks * 8 + t + 4) * BSTR + cb];
                #pragma unroll
                for (int mt = 0; mt < 2; mt++) {
                    mma8(acc[mt][nt], afh[mt], b0h, b1h);
                    mma8(acc[mt][nt], afh[mt], b0l, b1l);
                    mma8(acc[mt][nt], afl[mt], b0h, b1h);
                }
            }
        }
    }

    // epilogue: double-row layout. r0 ≡ g (mod 8); tv=g&3, sv=g>>2.
    const int tv = g & 3, sv = g >> 2;
    #pragma unroll
    for (int mt = 0; mt < 2; mt++) {
        int r0 = m0 + wm * 32 + mt * 16 + g;
        int jg0 = r0 >> 3;
        #pragma unroll
        for (int nt = 0; nt < 2; nt++) {
            int col = n0 + wn * 16 + nt * 8 + 2 * t;
            int hh = col >> 5, c = col & 31;
            float bv0 = bias[col], bv1 = bias[col + 1];
            float z0 = __uint_as_float(tf32r(acc[mt][nt][0] + bv0));
            float z1 = __uint_as_float(tf32r(acc[mt][nt][1] + bv1));
            float z2 = __uint_as_float(tf32r(acc[mt][nt][2] + bv0));
            float z3 = __uint_as_float(tf32r(acc[mt][nt][3] + bv1));
            size_t b0i = ((size_t)(hh * 512 + jg0) * 4 + tv) * 64 + sv;
            size_t b1i = ((size_t)(hh * 512 + jg0 + 1) * 4 + tv) * 64 + sv;
            out[b0i + 2 * c] = z0;  out[b0i + 2 * (c + 1)] = z1;
            out[b1i + 2 * c] = z2;  out[b1i + 2 * (c + 1)] = z3;
        }
    }
}

// ---------------------------------------------------------------------------
// Final linear, split-tf32: out = xcat @ lw^T + lb (known-good)
// ---------------------------------------------------------------------------
__global__ __launch_bounds__(256) void final_tc_kernel(
    const float* __restrict__ xcat, const float* __restrict__ lw,
    const float* __restrict__ lb, float* __restrict__ out)
{
    __shared__ uint32_t Ah[64 * 36], Al[64 * 36];
    __shared__ uint32_t Bh[32 * BSTR2], Bl[32 * BSTR2];

    const int tid = threadIdx.x;
    const int w = tid >> 5, lane = tid & 31;
    const int g = lane >> 2, t = lane & 3;
    const int wm = w & 1, wn = w >> 1;
    const int m0 = blockIdx.x * 64;
    const int n0 = blockIdx.y * 64;

    float acc[2][2][4] = {};

    for (int k0 = 0; k0 < 256; k0 += 32) {
        __syncthreads();
        #pragma unroll
        for (int i = 0; i < 2; i++) {
            int idx = tid + 256 * i;
            int row = idx >> 3;
            int col = (idx & 7) * 4;
            float4 v = *reinterpret_cast<const float4*>(
                &xcat[(size_t)(m0 + row) * HID + k0 + col]);
            uint4 h, l;
            split2(v.x, h.x, l.x); split2(v.y, h.y, l.y);
            split2(v.z, h.z, l.z); split2(v.w, h.w, l.w);
            *reinterpret_cast<uint4*>(&Ah[row * 36 + col]) = h;
            *reinterpret_cast<uint4*>(&Al[row * 36 + col]) = l;
        }
        #pragma unroll
        for (int i = 0; i < 2; i++) {
            int idx = tid + 256 * i;
            int c = idx >> 3;
            int kq = (idx & 7) * 4;
            float4 v = *reinterpret_cast<const float4*>(
                &lw[(size_t)(n0 + c) * HID + k0 + kq]);
            uint32_t h0, l0v, h1, l1v, h2, l2v, h3, l3v;
            split2(v.x, h0, l0v); split2(v.y, h1, l1v);
            split2(v.z, h2, l2v); split2(v.w, h3, l3v);
            Bh[(kq + 0) * BSTR2 + c] = h0;  Bl[(kq + 0) * BSTR2 + c] = l0v;
            Bh[(kq + 1) * BSTR2 + c] = h1;  Bl[(kq + 1) * BSTR2 + c] = l1v;
            Bh[(kq + 2) * BSTR2 + c] = h2;  Bl[(kq + 2) * BSTR2 + c] = l2v;
            Bh[(kq + 3) * BSTR2 + c] = h3;  Bl[(kq + 3) * BSTR2 + c] = l3v;
        }
        __syncthreads();

        #pragma unroll
        for (int ks = 0; ks < 4; ks++) {
            uint32_t afh[2][4], afl[2][4];
            #pragma unroll
            for (int mt = 0; mt < 2; mt++) {
                int rb = (wm * 32 + mt * 16) * 36 + ks * 8 + t;
                afh[mt][0] = Ah[rb + g * 36];
                afh[mt][1] = Ah[rb + (g + 8) * 36];
                afh[mt][2] = Ah[rb + g * 36 + 4];
                afh[mt][3] = Ah[rb + (g + 8) * 36 + 4];
                afl[mt][0] = Al[rb + g * 36];
                afl[mt][1] = Al[rb + (g + 8) * 36];
                afl[mt][2] = Al[rb + g * 36 + 4];
                afl[mt][3] = Al[rb + (g + 8) * 36 + 4];
            }
            #pragma unroll
            for (int nt = 0; nt < 2; nt++) {
                int cb = wn * 16 + nt * 8 + g;
                uint32_t b0h = Bh[(ks * 8 + t) * BSTR2 + cb];
                uint32_t b1h = Bh[(ks * 8 + t + 4) * BSTR2 + cb];
                uint32_t b0l = Bl[(ks * 8 + t) * BSTR2 + cb];
                uint32_t b1l = Bl[(ks * 8 + t + 4) * BSTR2 + cb];
                #pragma unroll
                for (int mt = 0; mt < 2; mt++) {
                    mma8(acc[mt][nt], afh[mt], b0h, b1h);
                    mma8(acc[mt][nt], afh[mt], b0l, b1l);
                    mma8(acc[mt][nt], afl[mt], b0h, b1h);
                }
            }
        }
    }

    #pragma unroll
    for (int mt = 0; mt < 2; mt++) {
        int r0 = m0 + wm * 32 + mt * 16 + g;
        #pragma unroll
        for (int nt = 0; nt < 2; nt++) {
            int col = n0 + wn * 16 + nt * 8 + 2 * t;
            float bv0 = lb[col], bv1 = lb[col + 1];
            *reinterpret_cast<float2*>(&out[(size_t)r0 * HID + col]) =
                make_float2(acc[mt][nt][0] + bv0, acc[mt][nt][1] + bv1);
            *reinterpret_cast<float2*>(&out[(size_t)(r0 + 8) * HID + col]) =
                make_float2(acc[mt][nt][2] + bv0, acc[mt][nt][3] + bv1);
        }
    }
}

// ---------------------------------------------------------------------------
// Flash attention: tf32 mma.sync, m-doubled, cp.async double-buffered,
// K row+column pair-permutations and V double-row layout -> all inner-loop
// SMEM reads are conflict-free LDS.64; shuffle-free P handoff; P fed to MMA
// via fp32 truncation (CUTLASS fast-tf32 path).
// Grid (N/128, HEADS); block 256 (8 warps).
// ---------------------------------------------------------------------------
__global__ __launch_bounds__(256) void attn_mma_kernel(
    const float* __restrict__ Qg, const float* __restrict__ Kg,
    const float* __restrict__ Vg, float* __restrict__ xcat)
{
    __shared__ __align__(16) char sbuf[SBUF_BYTES];
    const uint32_t sb = smem_u32(sbuf);

    const int tid = threadIdx.x;
    const int w = tid >> 5;
    const int lane = tid & 31;
    const int g = lane >> 2;
    const int t = lane & 3;
    const int h = blockIdx.y;
    const int q0 = blockIdx.x * QBLK;
    const int wm = w >> 1;
    const int m0 = wm * 32;
    const int c0 = (w & 1) * 32;      // KV col half
    const int jb = (c0 >> 3);         // base 8-row group of this warp's half

    const float* Qh = Qg + (size_t)h * N_TOK * HD;
    const float* Kh = Kg + (size_t)h * N_TOK * HD;
    const float* Vh = Vg + (size_t)h * N_TOK * HD;

    // ---- Q fragments (pre-scaled + pre-rounded bits, direct load) ----
    uint32_t qf[2][4][4];
    #pragma unroll
    for (int mt = 0; mt < 2; mt++) {
        const float* qr0 = Qh + (size_t)(q0 + m0 + mt * 16 + g) * HD;
        const float* qr1 = qr0 + 8 * HD;
        #pragma unroll
        for (int s = 0; s < 4; s++) {
            qf[mt][s][0] = __float_as_uint(qr0[8 * s + t]);
            qf[mt][s][1] = __float_as_uint(qr1[8 * s + t]);
            qf[mt][s][2] = __float_as_uint(qr0[8 * s + t + 4]);
            qf[mt][s][3] = __float_as_uint(qr1[8 * s + t + 4]);
        }
    }

    float of[2][4][4] = {};
    float l[2][2] = {};

    // ---- fill geometry ----
    const int frow = tid >> 3;            // 0..31 (K rows frow, frow+32)
    const int fb = (tid & 7) * 16;        // byte offset within 128B K row
    const int ks0 = slotmap(frow);
    const int ks1 = slotmap(frow + 32);
    // V chunks: q in {tid, tid+256}; dr = q>>4, 16B piece (q&15)
    const int vq0 = tid, vq1 = tid + 256;

    #define K_FILL(kb_, base_) do { \
        const char* kg_ = (const char*)(Kh + (size_t)((kb_) * KBLK + frow) * HD) + fb; \
        cp16((base_) + ks0 * (KSTR * 4) + fb, kg_); \
        cp16((base_) + ks1 * (KSTR * 4) + fb, kg_ + 32 * HD * 4); \
    } while (0)
    #define V_FILL(kb_, base_) do { \
        int q_ = vq0; \
        const float* vs_ = Vh + ((size_t)(8 * (kb_) + (q_ >> 6)) * 4 + ((q_ >> 4) & 3)) * 64 + (q_ & 15) * 4; \
        cp16((base_) + KBYTES + (q_ >> 4) * (DVS * 4) + (q_ & 15) * 16, vs_); \
        q_ = vq1; \
        vs_ = Vh + ((size_t)(8 * (kb_) + (q_ >> 6)) * 4 + ((q_ >> 4) & 3)) * 64 + (q_ & 15) * 4; \
        cp16((base_) + KBYTES + (q_ >> 4) * (DVS * 4) + (q_ & 15) * 16, vs_); \
    } while (0)

    // preload tile 0 into stage 0
    K_FILL(0, sb);
    V_FILL(0, sb);
    CP_COMMIT();

    for (int kb = 0; kb < NITER; kb++) {
        CP_WAIT0();
        __syncthreads();   // tile kb visible; all warps done with kb-1

        const int stage = kb & 1;
        if (kb + 1 < NITER) {
            const uint32_t nb = sb + (stage ^ 1) * STAGE_BYTES;
            K_FILL(kb + 1, nb);
            V_FILL(kb + 1, nb);
            CP_COMMIT();
        }

        const uint32_t* Ksp = reinterpret_cast<const uint32_t*>(sbuf + stage * STAGE_BYTES);
        const uint32_t* Vsp = reinterpret_cast<const uint32_t*>(sbuf + stage * STAGE_BYTES + KBYTES);

        #pragma unroll
        for (int j = 0; j < 4; j++) {
            // ---- K fragments: 4 conflict-free LDS.64 ----
            const uint32_t* kbp = &Ksp[(c0 + 8 * j + g) * KSTR + 2 * t];
            uint2 kp0 = *reinterpret_cast<const uint2*>(kbp);
            uint2 kp1 = *reinterpret_cast<const uint2*>(kbp + 8);
            uint2 kp2 = *reinterpret_cast<const uint2*>(kbp + 16);
            uint2 kp3 = *reinterpret_cast<const uint2*>(kbp + 24);

            float sf[2][4] = {};
            #pragma unroll
            for (int mt = 0; mt < 2; mt++) {
                mma8(sf[mt], qf[mt][0], kp0.x, kp0.y);
                mma8(sf[mt], qf[mt][1], kp1.x, kp1.y);
                mma8(sf[mt], qf[mt][2], kp2.x, kp2.y);
                mma8(sf[mt], qf[mt][3], kp3.x, kp3.y);
            }

            // ---- V fragments: 4 conflict-free LDS.64 (rows t & t+4 paired) ----
            const uint32_t* vbp = &Vsp[((jb + j) * 4 + t) * DVS + 2 * g];
            uint2 v0 = *reinterpret_cast<const uint2*>(vbp);
            uint2 v1 = *reinterpret_cast<const uint2*>(vbp + 16);
            uint2 v2 = *reinterpret_cast<const uint2*>(vbp + 32);
            uint2 v3 = *reinterpret_cast<const uint2*>(vbp + 48);

            #pragma unroll
            for (int mt = 0; mt < 2; mt++) {
                // C-fragment (K rows pair-permuted):
                //   sf[0]=P[g][t]  sf[1]=P[g][t+4]  sf[2]=P[g+8][t]  sf[3]=P[g+8][t+4]
                float e0 = exp2f(sf[mt][0]);
                float e1 = exp2f(sf[mt][1]);
                float e2 = exp2f(sf[mt][2]);
                float e3 = exp2f(sf[mt][3]);
                l[mt][0] += e0 + e1;
                l[mt][1] += e2 + e3;

                // A-layout directly; fp32 bits -> HW tf32 truncation
                uint32_t pa[4];
                pa[0] = __float_as_uint(e0);
                pa[1] = __float_as_uint(e2);
                pa[2] = __float_as_uint(e1);
                pa[3] = __float_as_uint(e3);

                mma8(of[mt][0], pa, v0.x, v0.y);
                mma8(of[mt][1], pa, v1.x, v1.y);
                mma8(of[mt][2], pa, v2.x, v2.y);
                mma8(of[mt][3], pa, v3.x, v3.y);
            }
        }
    }

    // ---- epilogue (sO/sL alias the KV buffers; safe after barrier) ----
    __syncthreads();
    float* sO = reinterpret_cast<float*>(sbuf);
    float* sL = reinterpret_cast<float*>(sbuf + QBLK * 34 * 4);

    #pragma unroll
    for (int mt = 0; mt < 2; mt++) {
        l[mt][0] += __shfl_xor_sync(0xffffffffu, l[mt][0], 1);
        l[mt][0] += __shfl_xor_sync(0xffffffffu, l[mt][0], 2);
        l[mt][1] += __shfl_xor_sync(0xffffffffu, l[mt][1], 1);
        l[mt][1] += __shfl_xor_sync(0xffffffffu, l[mt][1], 2);
    }

    if (w & 1) {
        #pragma unroll
        for (int mt = 0; mt < 2; mt++) {
            int r = m0 + mt * 16 + g;
            if (t == 0) { sL[r] = l[mt][0]; sL[r + 8] = l[mt][1]; }
            #pragma unroll
            for (int nn = 0; nn < 4; nn++) {
                *reinterpret_cast<float2*>(&sO[r * 34 + 8 * nn + 2 * t]) =
                    make_float2(of[mt][nn][0], of[mt][nn][1]);
                *reinterpret_cast<float2*>(&sO[(r + 8) * 34 + 8 * nn + 2 * t]) =
                    make_float2(of[mt][nn][2], of[mt][nn][3]);
            }
        }
    }
    __syncthreads();
    if (!(w & 1)) {
        #pragma unroll
        for (int mt = 0; mt < 2; mt++) {
            int r = m0 + mt * 16 + g;
            float L0 = l[mt][0] + sL[r];
            float L1 = l[mt][1] + sL[r + 8];
            float i0 = 1.0f / L0, i1 = 1.0f / L1;
            #pragma unroll
            for (int nn = 0; nn < 4; nn++) {
                float2 a = *reinterpret_cast<const float2*>(&sO[r * 34 + 8 * nn + 2 * t]);
                float2 b = *reinterpret_cast<const float2*>(&sO[(r + 8) * 34 + 8 * nn + 2 * t]);
                *reinterpret_cast<float2*>(
                    &xcat[(size_t)(q0 + r) * HID + h * HD + 8 * nn + 2 * t]) =
                    make_float2((of[mt][nn][0] + a.x) * i0, (of[mt][nn][1] + a.y) * i0);
                *reinterpret_cast<float2*>(
                    &xcat[(size_t)(q0 + r + 8) * HID + h * HD + 8 * nn + 2 * t]) =
                    make_float2((of[mt][nn][2] + b.x) * i1, (of[mt][nn][3] + b.y) * i1);
            }
        }
    }
}

// ---------------------------------------------------------------------------
extern "C" void kernel_launch(void* const* d_in, const int* in_sizes, int n_in,
                              void* d_out, int out_size)
{
    const float* x   = (const float*)d_in[0];
    const float* peQ = (const float*)d_in[1];
    const float* peK = (const float*)d_in[2];
    const float* WQ  = (const float*)d_in[4];
    const float* WK  = (const float*)d_in[5];
    const float* WV  = (const float*)d_in[6];
    const float* Qb  = (const float*)d_in[7];
    const float* Kb  = (const float*)d_in[8];
    const float* Vb  = (const float*)d_in[9];
    const float* lw  = (const float*)d_in[10];
    const float* lb  = (const float*)d_in[11];
    float* out = (float*)d_out;

    float *qp, *kp, *vp, *xc;
    cudaGetSymbolAddress((void**)&qp, g_Q);
    cudaGetSymbolAddress((void**)&kp, g_K);
    cudaGetSymbolAddress((void**)&vp, g_V);
    cudaGetSymbolAddress((void**)&xc, g_xcat);

    projqk_kernel<<<dim3(N_TOK / 128, HID / 64, 2), 256>>>(
        x, peQ, peK, WQ, WK, Qb, Kb, qp, kp);
    projv_tc_kernel<<<dim3(N_TOK / 64, HID / 64), 256>>>(x, WV, Vb, vp);
    attn_mma_kernel<<<dim3(N_TOK / QBLK, HEADS), 256>>>(qp, kp, vp, xc);
    final_tc_kernel<<<dim3(N_TOK / 64, HID / 64), 256>>>(xc, lw, lb, out);
}